// round 14
// baseline (speedup 1.0000x reference)
#include <cuda_runtime.h>
#include <cuda_bf16.h>
#include <math.h>
#include <stdint.h>

// ---------------------------------------------------------------------------
// Problem constants
// ---------------------------------------------------------------------------
#define BB     8
#define SS     2048
#define TT     (BB*SS)
#define DM     256
#define DI     512
#define DSTATE 16
#define DCONV  4
#define NVOCAB 256
#define LOG_VOCAB_F 5.5451774444795623f
#define RMS_EPS 1.1920928955078125e-7f
#define LOG2E_F 1.4426950408889634f

typedef __nv_bfloat16 bf16;

// ---------------------------------------------------------------------------
// Scratch
// ---------------------------------------------------------------------------
__device__ float g_x    [TT * DM];        // residual stream fp32
__device__ bf16  g_xh   [TT * DM];        // residual stream bf16
__device__ bf16  g_xinzh[TT * 2 * DI];    // in_proj out (x_in | z) bf16
__device__ bf16  g_xch  [TT * DI];        // conv+silu out bf16
__device__ bf16  g_dth  [TT * DI];        // dt pre-activation bf16
__device__ float g_Bm   [TT * DSTATE];    // B matrix fp32
__device__ bf16  g_uh   [TT * DI];        // gated y bf16
__device__ float g_ent  [TT];
__device__ int   g_pstart[BB * SS];
__device__ int   g_np    [BB];

// bf16 transposed weights [N,K] row-major, packed
#define WOFF_IN(l)   ((size_t)(l) * 1024 * 256)
#define WOFF_OUT(l)  (524288u + (size_t)(l) * 256 * 512)
#define WOFF_HEAD    (786432u)
__device__ bf16 g_wbf[851968];
// merged dt + x_proj(B half) weights: [640][512] per layer
// rows 0..511 = dtW^T, 512..527 = x_proj B^T, 528..639 zero pad (128-wide tiles)
#define NMERGE 640
__device__ bf16 g_wdtm[2 * NMERGE * 512];

// ---------------------------------------------------------------------------
// Weight prep + embedding, ALL in one launch.
// ---------------------------------------------------------------------------
__global__ void prep_kernel(const float* __restrict__ inW,
                            const float* __restrict__ dtW,
                            const float* __restrict__ outW,
                            const float* __restrict__ headW,
                            const float* __restrict__ xpW,
                            const int* __restrict__ bytes,
                            const float* __restrict__ embW,
                            bf16* __restrict__ wout,
                            bf16* __restrict__ wdtm,
                            float* __restrict__ x,
                            bf16* __restrict__ xh) {
    __shared__ float tile[32][33];
    int blk = blockIdx.x;
    int tx = threadIdx.x & 31, ty = threadIdx.x >> 5;

    if (blk >= 1384) {               // embedding: 4096 blocks, 4 elems/thread
        int vid = (blk - 1384) * 256 + threadIdx.x;
        int t = vid >> 6;
        int d4 = (vid & 63) * 4;
        float4 v = *reinterpret_cast<const float4*>(&embW[bytes[t] * DM + d4]);
        *reinterpret_cast<float4*>(&x[(size_t)t * DM + d4]) = v;
        __nv_bfloat162 h0 = __float22bfloat162_rn(make_float2(v.x, v.y));
        __nv_bfloat162 h1 = __float22bfloat162_rn(make_float2(v.z, v.w));
        uint32_t u0 = *reinterpret_cast<uint32_t*>(&h0);
        uint32_t u1 = *reinterpret_cast<uint32_t*>(&h1);
        *reinterpret_cast<uint2*>(&xh[(size_t)t * DM + d4]) = make_uint2(u0, u1);
        return;
    }
    if (blk >= 1376) {               // zero-fill pad rows 528..639
        int idx = blk - 1376;
        int l = idx >> 2, part = idx & 3;
        bf16* O = wdtm + (size_t)l * NMERGE * 512 + (528 + part * 28) * 512;
        for (int i = threadIdx.x; i < 28 * 512; i += 256) O[i] = __float2bfloat16_rn(0.f);
        return;
    }
    if (blk >= 1344) {               // x_proj B half transpose -> rows 512..527
        int idx = blk - 1344;
        int l = idx >> 4, t = idx & 15;
        const float* W = xpW + (size_t)l * DI * 2 * DSTATE;
        bf16* O = wdtm + (size_t)l * NMERGE * 512;
        int kb = t * 32;
        #pragma unroll
        for (int r = ty; r < 32; r += 8)
            tile[r][tx] = W[(size_t)(kb + r) * 32 + tx];
        __syncthreads();
        for (int r = ty; r < 16; r += 8)
            O[(size_t)(512 + r) * 512 + kb + tx] = __float2bfloat16_rn(tile[tx][r]);
        return;
    }

    const float* W; bf16* O; int K, N, t;
    if (blk < 512)       { int l = blk >> 8;        t = blk & 255;        W = inW  + (size_t)l*DM*2*DI; O = wout + WOFF_IN(l);            K = DM; N = 2*DI; }
    else if (blk < 1024) { int l = (blk-512) >> 8;  t = blk & 255;        W = dtW  + (size_t)l*DI*DI;   O = wdtm + (size_t)l*NMERGE*512;  K = DI; N = DI; }
    else if (blk < 1280) { int l = (blk-1024) >> 7; t = (blk-1024) & 127; W = outW + (size_t)l*DI*DM;   O = wout + WOFF_OUT(l);           K = DI; N = DM; }
    else                 { t = blk - 1280;          W = headW;            O = wout + WOFF_HEAD;         K = DM; N = NVOCAB; }
    int ncols = N >> 5;
    int nb = (t % ncols) * 32, kb = (t / ncols) * 32;
    #pragma unroll
    for (int r = ty; r < 32; r += 8)
        tile[r][tx] = W[(size_t)(kb + r) * N + nb + tx];
    __syncthreads();
    #pragma unroll
    for (int r = ty; r < 32; r += 8)
        O[(size_t)(nb + r) * K + kb + tx] = __float2bfloat16_rn(tile[tx][r]);
}

// ---------------------------------------------------------------------------
// mma helpers
// ---------------------------------------------------------------------------
__device__ __forceinline__ void cp_async16(void* smem, const void* gmem) {
    uint32_t s = (uint32_t)__cvta_generic_to_shared(smem);
    asm volatile("cp.async.cg.shared.global [%0], [%1], 16;" :: "r"(s), "l"(gmem));
}
__device__ __forceinline__ void ldsm_x4(uint32_t& r0, uint32_t& r1,
                                        uint32_t& r2, uint32_t& r3, uint32_t saddr) {
    asm volatile("ldmatrix.sync.aligned.m8n8.x4.shared.b16 {%0,%1,%2,%3}, [%4];"
        : "=r"(r0), "=r"(r1), "=r"(r2), "=r"(r3) : "r"(saddr));
}
__device__ __forceinline__ void mma16816(float* c, const uint32_t* a, const uint32_t* b) {
    asm volatile(
        "mma.sync.aligned.m16n8k16.row.col.f32.bf16.bf16.f32 "
        "{%0,%1,%2,%3},{%4,%5,%6,%7},{%8,%9},{%0,%1,%2,%3};"
        : "+f"(c[0]), "+f"(c[1]), "+f"(c[2]), "+f"(c[3])
        : "r"(a[0]), "r"(a[1]), "r"(a[2]), "r"(a[3]), "r"(b[0]), "r"(b[1]));
}
__device__ __forceinline__ uint32_t packbf(float a, float b) {
    __nv_bfloat162 h = __float22bfloat162_rn(make_float2(a, b));
    return *reinterpret_cast<uint32_t*>(&h);
}

#define ASTR 40

// ---------------------------------------------------------------------------
// 128x128x32 bf16 tensor-core GEMM, 256 threads, 3-stage cp.async pipeline,
// ONE __syncthreads per K-iter. Optional fp32 aux col split:
//   cols < nSplit -> bf16 C;  nSplit..nSplit+15 -> fp32 Caux;  rest dropped.
// ---------------------------------------------------------------------------
#define GBM 128
#define GBN 128
#define STG_A (GBM * ASTR)            // halves per A stage
#define STG_B (GBN * ASTR)            // halves per B stage
#define STG_T (STG_A + STG_B)         // halves per stage
#define G128_SMEM (3 * STG_T * 2)     // 61440 bytes

__global__ void __launch_bounds__(256)
mma_gemm128_kernel(const bf16* __restrict__ A, int lda,
                   const bf16* __restrict__ Bt, int ldb,
                   bf16* __restrict__ C, int ldc,
                   float* __restrict__ Caux, int nSplit,
                   int K) {
    extern __shared__ __align__(16) bf16 smem[];   // [3][STG_T]: A then B per stage

    const int tid  = threadIdx.x;
    const int lane = tid & 31;
    const int g    = lane >> 2;
    const int tg   = lane & 3;
    const int warp = tid >> 5;
    const int wm   = warp & 3;           // 4 warp rows x 32
    const int wn   = warp >> 2;          // 2 warp cols x 64
    const int mBase = wm * 32;
    const int nBase = wn * 64;
    const int rowBase = blockIdx.y * GBM;
    const int colBase = blockIdx.x * GBN;

    const int t4 = lane >> 3;
    const int l7 = lane & 7;
    const int aRowL = (t4 & 1) * 8 + l7;
    const int aColL = (t4 >> 1) * 8;
    const int bRowL = (t4 >> 1) * 8 + l7;
    const int bColL = (t4 & 1) * 8;
    const uint32_t sm_u = (uint32_t)__cvta_generic_to_shared(smem);

    const int cRow = tid >> 2, cKc = tid & 3;
    const bf16* Ab = A + (size_t)rowBase * lda;
    const bf16* Bb = Bt + (size_t)colBase * ldb;

    float acc[2][8][4];
    #pragma unroll
    for (int mi = 0; mi < 2; mi++)
        #pragma unroll
        for (int ni = 0; ni < 8; ni++)
            #pragma unroll
            for (int c = 0; c < 4; c++) acc[mi][ni][c] = 0.f;

    const int nIter = K / 32;

    // prologue: stages 0 and 1
    #pragma unroll
    for (int s = 0; s < 2; s++) {
        bf16* sA = smem + s * STG_T;
        bf16* sB = sA + STG_A;
        int k0 = s * 32;
        cp_async16(&sA[cRow * ASTR + cKc * 8],        Ab + (size_t)cRow * lda + k0 + cKc * 8);
        cp_async16(&sA[(cRow + 64) * ASTR + cKc * 8], Ab + (size_t)(cRow + 64) * lda + k0 + cKc * 8);
        cp_async16(&sB[cRow * ASTR + cKc * 8],        Bb + (size_t)cRow * ldb + k0 + cKc * 8);
        cp_async16(&sB[(cRow + 64) * ASTR + cKc * 8], Bb + (size_t)(cRow + 64) * ldb + k0 + cKc * 8);
        asm volatile("cp.async.commit_group;");
    }

    for (int it = 0; it < nIter; ++it) {
        // stage `it` data committed in group #it; allow 1 newer group pending
        asm volatile("cp.async.wait_group 1;");
        __syncthreads();   // also fences: all warps past compute of stage it-1

        // prefetch stage it+2 (empty commit keeps group accounting uniform)
        int pf = it + 2;
        if (pf < nIter) {
            int st = pf % 3;
            bf16* sA = smem + st * STG_T;
            bf16* sB = sA + STG_A;
            int k0 = pf * 32;
            cp_async16(&sA[cRow * ASTR + cKc * 8],        Ab + (size_t)cRow * lda + k0 + cKc * 8);
            cp_async16(&sA[(cRow + 64) * ASTR + cKc * 8], Ab + (size_t)(cRow + 64) * lda + k0 + cKc * 8);
            cp_async16(&sB[cRow * ASTR + cKc * 8],        Bb + (size_t)cRow * ldb + k0 + cKc * 8);
            cp_async16(&sB[(cRow + 64) * ASTR + cKc * 8], Bb + (size_t)(cRow + 64) * ldb + k0 + cKc * 8);
        }
        asm volatile("cp.async.commit_group;");

        const int buf = it % 3;
        const uint32_t aBuf = sm_u + buf * (STG_T * 2);
        const uint32_t bBuf = aBuf + STG_A * 2;

        #pragma unroll
        for (int ks = 0; ks < 2; ks++) {
            uint32_t af[2][4], bfr[8][2];
            #pragma unroll
            for (int mi = 0; mi < 2; mi++) {
                uint32_t a_lds = aBuf +
                    ((mBase + mi * 16 + aRowL) * ASTR + ks * 16 + aColL) * 2;
                ldsm_x4(af[mi][0], af[mi][1], af[mi][2], af[mi][3], a_lds);
            }
            #pragma unroll
            for (int p = 0; p < 4; p++) {
                uint32_t b_lds = bBuf +
                    ((nBase + p * 16 + bRowL) * ASTR + ks * 16 + bColL) * 2;
                ldsm_x4(bfr[2*p][0], bfr[2*p][1], bfr[2*p+1][0], bfr[2*p+1][1], b_lds);
            }
            #pragma unroll
            for (int mi = 0; mi < 2; mi++)
                #pragma unroll
                for (int ni = 0; ni < 8; ni++)
                    mma16816(acc[mi][ni], af[mi], bfr[ni]);
        }
    }

    #pragma unroll
    for (int mi = 0; mi < 2; mi++)
        #pragma unroll
        for (int ni = 0; ni < 8; ni++) {
            int row0 = rowBase + mBase + mi * 16 + g;
            int gcol = colBase + nBase + ni * 8 + tg * 2;
            if (gcol < nSplit) {
                *reinterpret_cast<uint32_t*>(&C[(size_t)row0 * ldc + gcol]) =
                    packbf(acc[mi][ni][0], acc[mi][ni][1]);
                *reinterpret_cast<uint32_t*>(&C[(size_t)(row0 + 8) * ldc + gcol]) =
                    packbf(acc[mi][ni][2], acc[mi][ni][3]);
            } else if (gcol < nSplit + DSTATE) {
                int ac = gcol - nSplit;
                *reinterpret_cast<float2*>(&Caux[(size_t)row0 * DSTATE + ac]) =
                    make_float2(acc[mi][ni][0], acc[mi][ni][1]);
                *reinterpret_cast<float2*>(&Caux[(size_t)(row0 + 8) * DSTATE + ac]) =
                    make_float2(acc[mi][ni][2], acc[mi][ni][3]);
            }
        }
}

// ---------------------------------------------------------------------------
// Wide-row fused GEMMs: BM=64, BN=256 (full row), BK=32, 512 threads.
// (unchanged 2-stage structure; epilogues reuse smem)
// ---------------------------------------------------------------------------
#define FBM 64
#define FSA (FBM * ASTR)
#define FSB (256 * ASTR)

__device__ __forceinline__ void fused_mainloop(
    const bf16* __restrict__ A, int lda,
    const bf16* __restrict__ Bt, int ldb,
    int K, int rowBase, bf16* sm, float acc[8][4]) {

    bf16* sAb = sm;
    bf16* sBb = sm + 2 * FSA;

    const int tid  = threadIdx.x;
    const int lane = tid & 31;
    const int warp = tid >> 5;
    const int wm   = warp & 3;
    const int wn   = warp >> 2;
    const int mBase = wm * 16;
    const int nBase = wn * 64;

    const int t4 = lane >> 3;
    const int l7 = lane & 7;
    const int aRowL = (t4 & 1) * 8 + l7;
    const int aColL = (t4 >> 1) * 8;
    const int bRowL = (t4 >> 1) * 8 + l7;
    const int bColL = (t4 & 1) * 8;
    const uint32_t sA_u = (uint32_t)__cvta_generic_to_shared(sAb);
    const uint32_t sB_u = (uint32_t)__cvta_generic_to_shared(sBb);

    const bf16* Ab = A + (size_t)rowBase * lda;
    const int aRow = tid >> 2, aKc = tid & 3;
    const int b0Row = tid >> 2, b0Kc = tid & 3;
    const int b1Row = (tid + 512) >> 2, b1Kc = tid & 3;

    const int nIter = K / 32;
    {
        if (tid < 256)
            cp_async16(&sAb[aRow * ASTR + aKc * 8], Ab + (size_t)aRow * lda + aKc * 8);
        cp_async16(&sBb[b0Row * ASTR + b0Kc * 8], Bt + (size_t)b0Row * ldb + b0Kc * 8);
        cp_async16(&sBb[b1Row * ASTR + b1Kc * 8], Bt + (size_t)b1Row * ldb + b1Kc * 8);
        asm volatile("cp.async.commit_group;");
    }

    for (int it = 0; it < nIter; ++it) {
        if (it + 1 < nIter) {
            int st = (it + 1) & 1;
            int k0 = (it + 1) * 32;
            if (tid < 256)
                cp_async16(&sAb[st * FSA + aRow * ASTR + aKc * 8],
                           Ab + (size_t)aRow * lda + k0 + aKc * 8);
            cp_async16(&sBb[st * FSB + b0Row * ASTR + b0Kc * 8],
                       Bt + (size_t)b0Row * ldb + k0 + b0Kc * 8);
            cp_async16(&sBb[st * FSB + b1Row * ASTR + b1Kc * 8],
                       Bt + (size_t)b1Row * ldb + k0 + b1Kc * 8);
            asm volatile("cp.async.commit_group;");
            asm volatile("cp.async.wait_group 1;");
        } else {
            asm volatile("cp.async.wait_group 0;");
        }
        __syncthreads();

        const int buf = it & 1;
        const uint32_t aBuf = sA_u + buf * (FSA * 2);
        const uint32_t bBuf = sB_u + buf * (FSB * 2);

        #pragma unroll
        for (int ks = 0; ks < 2; ks++) {
            uint32_t af[4], bfr[8][2];
            uint32_t a_lds = aBuf + ((mBase + aRowL) * ASTR + ks * 16 + aColL) * 2;
            ldsm_x4(af[0], af[1], af[2], af[3], a_lds);
            #pragma unroll
            for (int p = 0; p < 4; p++) {
                uint32_t b_lds = bBuf +
                    ((nBase + p * 16 + bRowL) * ASTR + ks * 16 + bColL) * 2;
                ldsm_x4(bfr[2*p][0], bfr[2*p][1], bfr[2*p+1][0], bfr[2*p+1][1], b_lds);
            }
            #pragma unroll
            for (int ni = 0; ni < 8; ni++)
                mma16816(acc[ni], af, bfr[ni]);
        }
        __syncthreads();
    }
}

// out_proj GEMM + residual + RMSNorm -> px (fp32) and pxh (bf16)
__global__ void __launch_bounds__(512)
gemm_rms_kernel(const bf16* __restrict__ A,
                const bf16* __restrict__ Bt,
                float* __restrict__ x, bf16* __restrict__ xh,
                const float* __restrict__ nw) {
    extern __shared__ __align__(16) char dsm[];
    bf16* sm = (bf16*)dsm;
    float acc[8][4];
    #pragma unroll
    for (int ni = 0; ni < 8; ni++)
        #pragma unroll
        for (int c = 0; c < 4; c++) acc[ni][c] = 0.f;

    const int rowBase = blockIdx.x * FBM;
    fused_mainloop(A, DI, Bt, DI, DI, rowBase, sm, acc);

    const int tid  = threadIdx.x;
    const int lane = tid & 31;
    const int g    = lane >> 2;
    const int tg   = lane & 3;
    const int warp = tid >> 5;
    const int wm   = warp & 3;
    const int wn   = warp >> 2;
    const int r0   = wm * 16 + g;
    const int r1   = r0 + 8;
    const int t0   = rowBase + r0;
    const int t1   = rowBase + r1;

    float pA = 0.f, pB = 0.f;
    #pragma unroll
    for (int ni = 0; ni < 8; ni++) {
        int col = wn * 64 + ni * 8 + tg * 2;
        float2 x0 = *reinterpret_cast<const float2*>(&x[(size_t)t0 * DM + col]);
        float2 x1 = *reinterpret_cast<const float2*>(&x[(size_t)t1 * DM + col]);
        acc[ni][0] += x0.x; acc[ni][1] += x0.y;
        acc[ni][2] += x1.x; acc[ni][3] += x1.y;
        pA += acc[ni][0]*acc[ni][0] + acc[ni][1]*acc[ni][1];
        pB += acc[ni][2]*acc[ni][2] + acc[ni][3]*acc[ni][3];
    }
    pA += __shfl_xor_sync(0xffffffffu, pA, 1);
    pA += __shfl_xor_sync(0xffffffffu, pA, 2);
    pB += __shfl_xor_sync(0xffffffffu, pB, 1);
    pB += __shfl_xor_sync(0xffffffffu, pB, 2);

    float* sred = (float*)dsm;
    __syncthreads();
    if (tg == 0) { sred[r0 * 4 + wn] = pA; sred[r1 * 4 + wn] = pB; }
    __syncthreads();
    if (tid < 64) {
        float s = sred[tid*4] + sred[tid*4+1] + sred[tid*4+2] + sred[tid*4+3];
        sred[256 + tid] = rsqrtf(s * (1.f / DM) + RMS_EPS);
    }
    __syncthreads();
    float sc0 = sred[256 + r0];
    float sc1 = sred[256 + r1];

    #pragma unroll
    for (int ni = 0; ni < 8; ni++) {
        int col = wn * 64 + ni * 8 + tg * 2;
        float2 w = *reinterpret_cast<const float2*>(&nw[col]);
        float o0 = acc[ni][0] * sc0 * w.x, o1 = acc[ni][1] * sc0 * w.y;
        float o2 = acc[ni][2] * sc1 * w.x, o3 = acc[ni][3] * sc1 * w.y;
        *reinterpret_cast<float2*>(&x[(size_t)t0 * DM + col]) = make_float2(o0, o1);
        *reinterpret_cast<float2*>(&x[(size_t)t1 * DM + col]) = make_float2(o2, o3);
        *reinterpret_cast<uint32_t*>(&xh[(size_t)t0 * DM + col]) = packbf(o0, o1);
        *reinterpret_cast<uint32_t*>(&xh[(size_t)t1 * DM + col]) = packbf(o2, o3);
    }
}

// head GEMM + softmax entropy -> ent[TT]
__global__ void __launch_bounds__(512)
gemm_ent_kernel(const bf16* __restrict__ A,
                const bf16* __restrict__ Bt,
                float* __restrict__ ent) {
    extern __shared__ __align__(16) char dsm[];
    bf16* sm = (bf16*)dsm;
    float acc[8][4];
    #pragma unroll
    for (int ni = 0; ni < 8; ni++)
        #pragma unroll
        for (int c = 0; c < 4; c++) acc[ni][c] = 0.f;

    const int rowBase = blockIdx.x * FBM;
    fused_mainloop(A, DM, Bt, DM, DM, rowBase, sm, acc);

    const int tid  = threadIdx.x;
    const int lane = tid & 31;
    const int g    = lane >> 2;
    const int tg   = lane & 3;
    const int warp = tid >> 5;
    const int wm   = warp & 3;
    const int wn   = warp >> 2;
    const int r0   = wm * 16 + g;
    const int r1   = r0 + 8;

    float mA = -1e30f, mB = -1e30f;
    #pragma unroll
    for (int ni = 0; ni < 8; ni++) {
        mA = fmaxf(mA, fmaxf(acc[ni][0], acc[ni][1]));
        mB = fmaxf(mB, fmaxf(acc[ni][2], acc[ni][3]));
    }
    mA = fmaxf(mA, __shfl_xor_sync(0xffffffffu, mA, 1));
    mA = fmaxf(mA, __shfl_xor_sync(0xffffffffu, mA, 2));
    mB = fmaxf(mB, __shfl_xor_sync(0xffffffffu, mB, 1));
    mB = fmaxf(mB, __shfl_xor_sync(0xffffffffu, mB, 2));

    float* sred = (float*)dsm;
    __syncthreads();
    if (tg == 0) { sred[r0 * 4 + wn] = mA; sred[r1 * 4 + wn] = mB; }
    __syncthreads();
    if (tid < 64)
        sred[256 + tid] = fmaxf(fmaxf(sred[tid*4], sred[tid*4+1]),
                                fmaxf(sred[tid*4+2], sred[tid*4+3]));
    __syncthreads();
    float rm0 = sred[256 + r0];
    float rm1 = sred[256 + r1];
    __syncthreads();

    float zA = 0.f, sAc = 0.f, zB = 0.f, sBc = 0.f;
    #pragma unroll
    for (int ni = 0; ni < 8; ni++) {
        float d0 = acc[ni][0] - rm0, d1 = acc[ni][1] - rm0;
        float d2 = acc[ni][2] - rm1, d3 = acc[ni][3] - rm1;
        float e0 = __expf(d0), e1 = __expf(d1), e2 = __expf(d2), e3 = __expf(d3);
        zA += e0 + e1;  sAc += e0 * d0 + e1 * d1;
        zB += e2 + e3;  sBc += e2 * d2 + e3 * d3;
    }
    zA  += __shfl_xor_sync(0xffffffffu, zA, 1);
    zA  += __shfl_xor_sync(0xffffffffu, zA, 2);
    sAc += __shfl_xor_sync(0xffffffffu, sAc, 1);
    sAc += __shfl_xor_sync(0xffffffffu, sAc, 2);
    zB  += __shfl_xor_sync(0xffffffffu, zB, 1);
    zB  += __shfl_xor_sync(0xffffffffu, zB, 2);
    sBc += __shfl_xor_sync(0xffffffffu, sBc, 1);
    sBc += __shfl_xor_sync(0xffffffffu, sBc, 2);

    if (tg == 0) {
        sred[r0 * 4 + wn] = zA;        sred[r1 * 4 + wn] = zB;
        sred[320 + r0 * 4 + wn] = sAc; sred[320 + r1 * 4 + wn] = sBc;
    }
    __syncthreads();
    if (tid < 64) {
        float Z = sred[tid*4] + sred[tid*4+1] + sred[tid*4+2] + sred[tid*4+3];
        float S = sred[320+tid*4] + sred[320+tid*4+1] + sred[320+tid*4+2] + sred[320+tid*4+3];
        ent[rowBase + tid] = (__logf(Z) - __fdividef(S, Z)) * (1.f / LOG_VOCAB_F);
    }
}

// ---------------------------------------------------------------------------
// Causal depthwise conv + bias + silu — register sliding window, 4 ch/thread
// ---------------------------------------------------------------------------
#define TCONV 16
__global__ void __launch_bounds__(256)
conv_silu_kernel(const bf16* __restrict__ xinzh,
                 const float* __restrict__ cw,
                 const float* __restrict__ cb,
                 bf16* __restrict__ xch) {
    const int tid = threadIdx.x;
    const int vec = tid & 127;
    const int tgrp = tid >> 7;
    const int dv = vec * 4;

    const int tokBlk = blockIdx.x;
    const int b = tokBlk / (SS / 32);
    const int sBase = (tokBlk % (SS / 32)) * 32 + tgrp * TCONV;

    float w[4][DCONV], bias[4];
    {
        float4 bv = *reinterpret_cast<const float4*>(&cb[dv]);
        bias[0] = bv.x; bias[1] = bv.y; bias[2] = bv.z; bias[3] = bv.w;
        #pragma unroll
        for (int j = 0; j < 4; j++) {
            float4 wv = *reinterpret_cast<const float4*>(&cw[(dv + j) * DCONV]);
            w[j][0] = wv.x; w[j][1] = wv.y; w[j][2] = wv.z; w[j][3] = wv.w;
        }
    }

    float p3[4], p2[4], p1[4];
    #pragma unroll
    for (int j = 0; j < 4; j++) { p3[j] = 0.f; p2[j] = 0.f; p1[j] = 0.f; }

    const bf16* rowBase = xinzh + (size_t)b * SS * (2 * DI) + dv;
    #define LOADROW(dst, s) { \
        uint2 raw = *reinterpret_cast<const uint2*>(rowBase + (size_t)(s) * (2 * DI)); \
        const __nv_bfloat162* h2 = reinterpret_cast<const __nv_bfloat162*>(&raw); \
        _Pragma("unroll") \
        for (int j = 0; j < 2; j++) { \
            float2 f = __bfloat1622float2(h2[j]); \
            dst[2*j] = f.x; dst[2*j+1] = f.y; } }

    if (sBase >= 3) { LOADROW(p3, sBase - 3); }
    if (sBase >= 2) { LOADROW(p2, sBase - 2); }
    if (sBase >= 1) { LOADROW(p1, sBase - 1); }

    bf16* outBase = xch + (size_t)b * SS * DI + dv;

    #pragma unroll
    for (int i = 0; i < TCONV; i++) {
        int s = sBase + i;
        float cur[4];
        LOADROW(cur, s);

        uint2 outv;
        uint32_t* o = reinterpret_cast<uint32_t*>(&outv);
        #pragma unroll
        for (int j = 0; j < 2; j++) {
            float a0 = bias[2*j], a1 = bias[2*j+1];
            a0 = fmaf(w[2*j][0],   p3[2*j],   a0);
            a1 = fmaf(w[2*j+1][0], p3[2*j+1], a1);
            a0 = fmaf(w[2*j][1],   p2[2*j],   a0);
            a1 = fmaf(w[2*j+1][1], p2[2*j+1], a1);
            a0 = fmaf(w[2*j][2],   p1[2*j],   a0);
            a1 = fmaf(w[2*j+1][2], p1[2*j+1], a1);
            a0 = fmaf(w[2*j][3],   cur[2*j],   a0);
            a1 = fmaf(w[2*j+1][3], cur[2*j+1], a1);
            float v0 = __fdividef(a0, 1.f + __expf(-a0));
            float v1 = __fdividef(a1, 1.f + __expf(-a1));
            o[j] = packbf(v0, v1);
        }
        *reinterpret_cast<uint2*>(outBase + (size_t)s * DI) = outv;

        #pragma unroll
        for (int j = 0; j < 4; j++) { p3[j] = p2[j]; p2[j] = p1[j]; p1[j] = cur[j]; }
    }
    #undef LOADROW
}

// ---------------------------------------------------------------------------
// Fused Mamba pointwise core (exp2-based MUFU path)
// ---------------------------------------------------------------------------
#define EW_TOKS 8
__global__ void mamba_ew_kernel(const bf16* __restrict__ dth,
                                const bf16* __restrict__ xch,
                                const bf16* __restrict__ xinzh,
                                const float* __restrict__ Bmat,
                                const float* __restrict__ Alog,
                                const float* __restrict__ dtb,
                                const float* __restrict__ Dp,
                                bf16* __restrict__ uh) {
    __shared__ float negAT[DSTATE][DI];   // pre-scaled by log2(e)
    __shared__ float sdtb[DI];
    __shared__ float sD[DI];
    __shared__ float sB[DSTATE];

    const int tid = threadIdx.x;
    for (int i = tid; i < DI * DSTATE; i += 256) {
        int d = i / DSTATE, n = i % DSTATE;
        negAT[n][d] = -__expf(Alog[i]) * LOG2E_F;
    }
    for (int i = tid; i < DI; i += 256) { sdtb[i] = dtb[i]; sD[i] = Dp[i]; }
    __syncthreads();

    for (int tok = 0; tok < EW_TOKS; tok++) {
        int t = blockIdx.x * EW_TOKS + tok;
        if (tid < DSTATE) sB[tid] = Bmat[t * DSTATE + tid];
        __syncthreads();

        #pragma unroll
        for (int rep = 0; rep < 2; rep++) {
            int d = tid + rep * 256;
            float v   = __bfloat162float(dth[(size_t)t * DI + d]) + sdtb[d];
            float dtv = fmaxf(v, 0.f) + __logf(1.f + __expf(-fabsf(v)));
            float xcv = __bfloat162float(xch[(size_t)t * DI + d]);
            float accn = 0.f;
            #pragma unroll
            for (int n = 0; n < DSTATE; n++)
                accn = fmaf(exp2f(negAT[n][d] * dtv), sB[n], accn);
            float yv = dtv * xcv * accn + sD[d] * xcv;
            float zv = __bfloat162float(xinzh[(size_t)t * (2 * DI) + DI + d]);
            uh[(size_t)t * DI + d] =
                __float2bfloat16_rn(yv * __fdividef(zv, 1.f + __expf(-zv)));
        }
        __syncthreads();
    }
}

// ---------------------------------------------------------------------------
// Parallel boundary computation (scan).
// ---------------------------------------------------------------------------
__global__ void boundary_kernel(const float* __restrict__ ent,
                                int* __restrict__ pstart,
                                int* __restrict__ np,
                                float* __restrict__ out_b2p) {
    __shared__ int sh[256];
    int b = blockIdx.x;
    int tid = threadIdx.x;
    int base = tid * 8;

    float e[8];
    #pragma unroll
    for (int i = 0; i < 8; i++) e[i] = ent[b * SS + base + i];

    int hard[8];
    int lasth = -1;
    #pragma unroll
    for (int i = 0; i < 8; i++) {
        hard[i] = (base + i == 0) || (e[i] > 0.5f);
        if (hard[i]) lasth = base + i;
    }

    sh[tid] = lasth;
    __syncthreads();
    for (int off = 1; off < 256; off <<= 1) {
        int u = sh[tid];
        int w = (tid >= off) ? sh[tid - off] : -1;
        __syncthreads();
        sh[tid] = max(u, w);
        __syncthreads();
    }
    int ph = (tid > 0) ? sh[tid - 1] : -1;

    int bnd[8];
    int cnt = 0;
    #pragma unroll
    for (int i = 0; i < 8; i++) {
        int s = base + i;
        if (hard[i]) ph = s;
        bnd[i] = hard[i] || (((s - ph) & 7) == 0);
        cnt += bnd[i];
    }

    __syncthreads();
    sh[tid] = cnt;
    __syncthreads();
    for (int off = 1; off < 256; off <<= 1) {
        int u = sh[tid];
        int w = (tid >= off) ? sh[tid - off] : 0;
        __syncthreads();
        sh[tid] = u + w;
        __syncthreads();
    }
    int pref = (tid > 0) ? sh[tid - 1] : 0;

    int c = 0;
    #pragma unroll
    for (int i = 0; i < 8; i++) {
        int s = base + i;
        c += bnd[i];
        int p = pref + c - 1;
        out_b2p[b * SS + s] = (float)p;
        if (bnd[i]) pstart[b * SS + p] = s;
    }
    if (tid == 255) np[b] = sh[255];
}

// ---------------------------------------------------------------------------
// Patch mean pooling
// ---------------------------------------------------------------------------
__global__ void pool_kernel(const float* __restrict__ be,
                            const int* __restrict__ pstart,
                            const int* __restrict__ np,
                            float* __restrict__ out_emb,
                            float* __restrict__ out_len) {
    int blk = blockIdx.x;
    int b = blk / SS;
    int p = blk - b * SS;
    int d = threadIdx.x;
    int npb = np[b];

    if (p < npb) {
        int s0 = pstart[b * SS + p];
        int s1 = (p + 1 < npb) ? pstart[b * SS + p + 1] : SS;
        float sum = 0.f;
        for (int s = s0; s < s1; s++)
            sum += be[(size_t)(b * SS + s) * DM + d];
        out_emb[(size_t)blk * DM + d] = sum / (float)(s1 - s0);
        if (d == 0) out_len[blk] = (float)(s1 - s0);
    } else {
        out_emb[(size_t)blk * DM + d] = 0.f;
        if (d == 0) out_len[blk] = 0.f;
    }
}

// ---------------------------------------------------------------------------
// Launch
// ---------------------------------------------------------------------------
#define FUSED_SMEM 51200

extern "C" void kernel_launch(void* const* d_in, const int* in_sizes, int n_in,
                              void* d_out, int out_size) {
    const int*   bytes = (const int*)  d_in[0];
    const float* be    = (const float*)d_in[1];
    const float* embW  = (const float*)d_in[2];
    const float* inW   = (const float*)d_in[3];
    const float* cw    = (const float*)d_in[4];
    const float* cb    = (const float*)d_in[5];
    const float* xpW   = (const float*)d_in[6];
    const float* dtW   = (const float*)d_in[7];
    const float* dtb   = (const float*)d_in[8];
    const float* Alog  = (const float*)d_in[9];
    const float* Dp    = (const float*)d_in[10];
    const float* outW  = (const float*)d_in[11];
    const float* nw    = (const float*)d_in[12];
    const float* headW = (const float*)d_in[13];
    float* out = (float*)d_out;

    static float *px=nullptr, *pB, *pent;
    static bf16 *pxh, *pxinzh, *pxch, *pdth, *puh, *pwbf, *pwdtm;
    static int *ppstart, *pnp;
    if (!px) {
        cudaGetSymbolAddress((void**)&px,     g_x);
        cudaGetSymbolAddress((void**)&pxh,    g_xh);
        cudaGetSymbolAddress((void**)&pxinzh, g_xinzh);
        cudaGetSymbolAddress((void**)&pxch,   g_xch);
        cudaGetSymbolAddress((void**)&pdth,   g_dth);
        cudaGetSymbolAddress((void**)&pB,     g_Bm);
        cudaGetSymbolAddress((void**)&puh,    g_uh);
        cudaGetSymbolAddress((void**)&pent,   g_ent);
        cudaGetSymbolAddress((void**)&pwbf,   g_wbf);
        cudaGetSymbolAddress((void**)&pwdtm,  g_wdtm);
        cudaGetSymbolAddress((void**)&ppstart,g_pstart);
        cudaGetSymbolAddress((void**)&pnp,    g_np);
        cudaFuncSetAttribute(gemm_rms_kernel,
            cudaFuncAttributeMaxDynamicSharedMemorySize, FUSED_SMEM);
        cudaFuncSetAttribute(gemm_ent_kernel,
            cudaFuncAttributeMaxDynamicSharedMemorySize, FUSED_SMEM);
        cudaFuncSetAttribute(mma_gemm128_kernel,
            cudaFuncAttributeMaxDynamicSharedMemorySize, G128_SMEM);
    }

    // 0) weight prep + embedding (single launch)
    prep_kernel<<<1384 + TT * DM / 1024, 256>>>(
        inW, dtW, outW, headW, xpW, bytes, embW, pwbf, pwdtm, px, pxh);

    // 1) two mamba blocks
    for (int l = 0; l < 2; l++) {
        // x @ in_proj -> xinz bf16  (N=1024, K=256)
        mma_gemm128_kernel<<<dim3(1024/GBN, TT/GBM), 256, G128_SMEM>>>(
            pxh, DM, pwbf + WOFF_IN(l), DM, pxinzh, 2 * DI, nullptr, 4096, DM);
        // depthwise conv + silu
        conv_silu_kernel<<<TT / 32, 256>>>(
            pxinzh, cw + (size_t)l * DI * DCONV, cb + (size_t)l * DI, pxch);
        // xc @ [dt_w | x_proj_B | pad] -> dt bf16 + Bmat fp32  (N=640, K=512)
        mma_gemm128_kernel<<<dim3(NMERGE/GBN, TT/GBM), 256, G128_SMEM>>>(
            pxch, DI, pwdtm + (size_t)l * NMERGE * 512, DI,
            pdth, DI, pB, 512, DI);
        // fused pointwise core
        mamba_ew_kernel<<<TT / EW_TOKS, 256>>>(
            pdth, pxch, pxinzh, pB,
            Alog + (size_t)l * DI * DSTATE, dtb + (size_t)l * DI,
            Dp + (size_t)l * DI, puh);
        // u @ out_w + residual + rmsnorm (fused)
        gemm_rms_kernel<<<TT / FBM, 512, FUSED_SMEM>>>(
            puh, pwbf + WOFF_OUT(l), px, pxh, nw + (size_t)l * DM);
    }

    // 2) head + entropy (fused)
    gemm_ent_kernel<<<TT / FBM, 512, FUSED_SMEM>>>(pxh, pwbf + WOFF_HEAD, pent);

    // 3) boundaries (parallel scan)
    boundary_kernel<<<BB, 256>>>(pent, ppstart, pnp, out + (size_t)TT * DM + TT);

    // 4) patch pooling
    pool_kernel<<<BB * SS, 256>>>(be, ppstart, pnp, out, out + (size_t)TT * DM);
}

// round 15
// speedup vs baseline: 1.0037x; 1.0037x over previous
#include <cuda_runtime.h>
#include <cuda_bf16.h>
#include <math.h>
#include <stdint.h>

// ---------------------------------------------------------------------------
// Problem constants
// ---------------------------------------------------------------------------
#define BB     8
#define SS     2048
#define TT     (BB*SS)
#define DM     256
#define DI     512
#define DSTATE 16
#define DCONV  4
#define NVOCAB 256
#define LOG_VOCAB_F 5.5451774444795623f
#define RMS_EPS 1.1920928955078125e-7f
#define LOG2E_F 1.4426950408889634f

typedef __nv_bfloat16 bf16;

// ---------------------------------------------------------------------------
// Scratch
// ---------------------------------------------------------------------------
__device__ float g_x    [TT * DM];        // residual stream fp32
__device__ bf16  g_xh   [TT * DM];        // residual stream bf16
__device__ bf16  g_xinzh[TT * 2 * DI];    // in_proj out (x_in | z) bf16
__device__ bf16  g_xch  [TT * DI];        // conv+silu out bf16
__device__ bf16  g_dth  [TT * DI];        // dt pre-activation bf16
__device__ float g_Bm   [TT * DSTATE];    // B matrix fp32
__device__ bf16  g_uh   [TT * DI];        // gated y bf16
__device__ float g_ent  [TT];
__device__ int   g_pstart[BB * SS];
__device__ int   g_np    [BB];

// bf16 transposed weights [N,K] row-major, packed
#define WOFF_IN(l)   ((size_t)(l) * 1024 * 256)
#define WOFF_OUT(l)  (524288u + (size_t)(l) * 256 * 512)
#define WOFF_HEAD    (786432u)
__device__ bf16 g_wbf[851968];
// merged dt + x_proj(B half) weights: [640][512] per layer
// rows 0..511 = dtW^T, 512..527 = x_proj B^T, 528..639 zero pad
#define NMERGE 640
__device__ bf16 g_wdtm[2 * NMERGE * 512];

// ---------------------------------------------------------------------------
// Weight prep + embedding, ALL in one launch.
// ---------------------------------------------------------------------------
__global__ void prep_kernel(const float* __restrict__ inW,
                            const float* __restrict__ dtW,
                            const float* __restrict__ outW,
                            const float* __restrict__ headW,
                            const float* __restrict__ xpW,
                            const int* __restrict__ bytes,
                            const float* __restrict__ embW,
                            bf16* __restrict__ wout,
                            bf16* __restrict__ wdtm,
                            float* __restrict__ x,
                            bf16* __restrict__ xh) {
    __shared__ float tile[32][33];
    int blk = blockIdx.x;
    int tx = threadIdx.x & 31, ty = threadIdx.x >> 5;

    if (blk >= 1384) {               // embedding: 4096 blocks, 4 elems/thread
        int vid = (blk - 1384) * 256 + threadIdx.x;
        int t = vid >> 6;
        int d4 = (vid & 63) * 4;
        float4 v = *reinterpret_cast<const float4*>(&embW[bytes[t] * DM + d4]);
        *reinterpret_cast<float4*>(&x[(size_t)t * DM + d4]) = v;
        __nv_bfloat162 h0 = __float22bfloat162_rn(make_float2(v.x, v.y));
        __nv_bfloat162 h1 = __float22bfloat162_rn(make_float2(v.z, v.w));
        uint32_t u0 = *reinterpret_cast<uint32_t*>(&h0);
        uint32_t u1 = *reinterpret_cast<uint32_t*>(&h1);
        *reinterpret_cast<uint2*>(&xh[(size_t)t * DM + d4]) = make_uint2(u0, u1);
        return;
    }
    if (blk >= 1376) {               // zero-fill pad rows 528..639
        int idx = blk - 1376;
        int l = idx >> 2, part = idx & 3;
        bf16* O = wdtm + (size_t)l * NMERGE * 512 + (528 + part * 28) * 512;
        for (int i = threadIdx.x; i < 28 * 512; i += 256) O[i] = __float2bfloat16_rn(0.f);
        return;
    }
    if (blk >= 1344) {               // x_proj B half transpose -> rows 512..527
        int idx = blk - 1344;
        int l = idx >> 4, t = idx & 15;
        const float* W = xpW + (size_t)l * DI * 2 * DSTATE;
        bf16* O = wdtm + (size_t)l * NMERGE * 512;
        int kb = t * 32;
        #pragma unroll
        for (int r = ty; r < 32; r += 8)
            tile[r][tx] = W[(size_t)(kb + r) * 32 + tx];
        __syncthreads();
        for (int r = ty; r < 16; r += 8)
            O[(size_t)(512 + r) * 512 + kb + tx] = __float2bfloat16_rn(tile[tx][r]);
        return;
    }

    const float* W; bf16* O; int K, N, t;
    if (blk < 512)       { int l = blk >> 8;        t = blk & 255;        W = inW  + (size_t)l*DM*2*DI; O = wout + WOFF_IN(l);            K = DM; N = 2*DI; }
    else if (blk < 1024) { int l = (blk-512) >> 8;  t = blk & 255;        W = dtW  + (size_t)l*DI*DI;   O = wdtm + (size_t)l*NMERGE*512;  K = DI; N = DI; }
    else if (blk < 1280) { int l = (blk-1024) >> 7; t = (blk-1024) & 127; W = outW + (size_t)l*DI*DM;   O = wout + WOFF_OUT(l);           K = DI; N = DM; }
    else                 { t = blk - 1280;          W = headW;            O = wout + WOFF_HEAD;         K = DM; N = NVOCAB; }
    int ncols = N >> 5;
    int nb = (t % ncols) * 32, kb = (t / ncols) * 32;
    #pragma unroll
    for (int r = ty; r < 32; r += 8)
        tile[r][tx] = W[(size_t)(kb + r) * N + nb + tx];
    __syncthreads();
    #pragma unroll
    for (int r = ty; r < 32; r += 8)
        O[(size_t)(nb + r) * K + kb + tx] = __float2bfloat16_rn(tile[tx][r]);
}

// ---------------------------------------------------------------------------
// mma helpers
// ---------------------------------------------------------------------------
__device__ __forceinline__ void cp_async16(void* smem, const void* gmem) {
    uint32_t s = (uint32_t)__cvta_generic_to_shared(smem);
    asm volatile("cp.async.cg.shared.global [%0], [%1], 16;" :: "r"(s), "l"(gmem));
}
__device__ __forceinline__ void ldsm_x4(uint32_t& r0, uint32_t& r1,
                                        uint32_t& r2, uint32_t& r3, uint32_t saddr) {
    asm volatile("ldmatrix.sync.aligned.m8n8.x4.shared.b16 {%0,%1,%2,%3}, [%4];"
        : "=r"(r0), "=r"(r1), "=r"(r2), "=r"(r3) : "r"(saddr));
}
__device__ __forceinline__ void mma16816(float* c, const uint32_t* a, const uint32_t* b) {
    asm volatile(
        "mma.sync.aligned.m16n8k16.row.col.f32.bf16.bf16.f32 "
        "{%0,%1,%2,%3},{%4,%5,%6,%7},{%8,%9},{%0,%1,%2,%3};"
        : "+f"(c[0]), "+f"(c[1]), "+f"(c[2]), "+f"(c[3])
        : "r"(a[0]), "r"(a[1]), "r"(a[2]), "r"(a[3]), "r"(b[0]), "r"(b[1]));
}
__device__ __forceinline__ uint32_t packbf(float a, float b) {
    __nv_bfloat162 h = __float22bfloat162_rn(make_float2(a, b));
    return *reinterpret_cast<uint32_t*>(&h);
}

#define ASTR 40

// ---------------------------------------------------------------------------
// 128x64x32 bf16 tensor-core GEMM, 256 threads (4x2 warps, 32x32 each),
// 3-stage cp.async pipeline, ONE __syncthreads per K-iter,
// __launch_bounds__(256,3) -> 3 blocks/SM (24 warps). Optional aux split.
// ---------------------------------------------------------------------------
#define GBM 128
#define GBN 64
#define STG_A (GBM * ASTR)            // halves per A stage
#define STG_B (GBN * ASTR)            // halves per B stage
#define STG_T (STG_A + STG_B)         // halves per stage
#define G128_SMEM (3 * STG_T * 2)     // 46080 bytes

__global__ void __launch_bounds__(256, 3)
mma_gemm128_kernel(const bf16* __restrict__ A, int lda,
                   const bf16* __restrict__ Bt, int ldb,
                   bf16* __restrict__ C, int ldc,
                   float* __restrict__ Caux, int nSplit,
                   int K) {
    extern __shared__ __align__(16) bf16 smem[];   // [3][STG_T]: A then B

    const int tid  = threadIdx.x;
    const int lane = tid & 31;
    const int g    = lane >> 2;
    const int tg   = lane & 3;
    const int warp = tid >> 5;
    const int wm   = warp & 3;           // 4 warp rows x 32
    const int wn   = warp >> 2;          // 2 warp cols x 32
    const int mBase = wm * 32;
    const int nBase = wn * 32;
    const int rowBase = blockIdx.y * GBM;
    const int colBase = blockIdx.x * GBN;

    const int t4 = lane >> 3;
    const int l7 = lane & 7;
    const int aRowL = (t4 & 1) * 8 + l7;
    const int aColL = (t4 >> 1) * 8;
    const int bRowL = (t4 >> 1) * 8 + l7;
    const int bColL = (t4 & 1) * 8;
    const uint32_t sm_u = (uint32_t)__cvta_generic_to_shared(smem);

    const int cRow = tid >> 2, cKc = tid & 3;
    const bf16* Ab = A + (size_t)rowBase * lda;
    const bf16* Bb = Bt + (size_t)colBase * ldb;

    float acc[2][4][4];
    #pragma unroll
    for (int mi = 0; mi < 2; mi++)
        #pragma unroll
        for (int ni = 0; ni < 4; ni++)
            #pragma unroll
            for (int c = 0; c < 4; c++) acc[mi][ni][c] = 0.f;

    const int nIter = K / 32;

    // prologue: stages 0 and 1
    #pragma unroll
    for (int s = 0; s < 2; s++) {
        bf16* sA = smem + s * STG_T;
        bf16* sB = sA + STG_A;
        int k0 = s * 32;
        cp_async16(&sA[cRow * ASTR + cKc * 8],        Ab + (size_t)cRow * lda + k0 + cKc * 8);
        cp_async16(&sA[(cRow + 64) * ASTR + cKc * 8], Ab + (size_t)(cRow + 64) * lda + k0 + cKc * 8);
        cp_async16(&sB[cRow * ASTR + cKc * 8],        Bb + (size_t)cRow * ldb + k0 + cKc * 8);
        asm volatile("cp.async.commit_group;");
    }

    for (int it = 0; it < nIter; ++it) {
        asm volatile("cp.async.wait_group 1;");
        __syncthreads();

        int pf = it + 2;
        if (pf < nIter) {
            int st = pf % 3;
            bf16* sA = smem + st * STG_T;
            bf16* sB = sA + STG_A;
            int k0 = pf * 32;
            cp_async16(&sA[cRow * ASTR + cKc * 8],        Ab + (size_t)cRow * lda + k0 + cKc * 8);
            cp_async16(&sA[(cRow + 64) * ASTR + cKc * 8], Ab + (size_t)(cRow + 64) * lda + k0 + cKc * 8);
            cp_async16(&sB[cRow * ASTR + cKc * 8],        Bb + (size_t)cRow * ldb + k0 + cKc * 8);
        }
        asm volatile("cp.async.commit_group;");

        const int buf = it % 3;
        const uint32_t aBuf = sm_u + buf * (STG_T * 2);
        const uint32_t bBuf = aBuf + STG_A * 2;

        #pragma unroll
        for (int ks = 0; ks < 2; ks++) {
            uint32_t af[2][4], bfr[4][2];
            #pragma unroll
            for (int mi = 0; mi < 2; mi++) {
                uint32_t a_lds = aBuf +
                    ((mBase + mi * 16 + aRowL) * ASTR + ks * 16 + aColL) * 2;
                ldsm_x4(af[mi][0], af[mi][1], af[mi][2], af[mi][3], a_lds);
            }
            #pragma unroll
            for (int p = 0; p < 2; p++) {
                uint32_t b_lds = bBuf +
                    ((nBase + p * 16 + bRowL) * ASTR + ks * 16 + bColL) * 2;
                ldsm_x4(bfr[2*p][0], bfr[2*p][1], bfr[2*p+1][0], bfr[2*p+1][1], b_lds);
            }
            #pragma unroll
            for (int mi = 0; mi < 2; mi++)
                #pragma unroll
                for (int ni = 0; ni < 4; ni++)
                    mma16816(acc[mi][ni], af[mi], bfr[ni]);
        }
    }

    #pragma unroll
    for (int mi = 0; mi < 2; mi++)
        #pragma unroll
        for (int ni = 0; ni < 4; ni++) {
            int row0 = rowBase + mBase + mi * 16 + g;
            int gcol = colBase + nBase + ni * 8 + tg * 2;
            if (gcol < nSplit) {
                *reinterpret_cast<uint32_t*>(&C[(size_t)row0 * ldc + gcol]) =
                    packbf(acc[mi][ni][0], acc[mi][ni][1]);
                *reinterpret_cast<uint32_t*>(&C[(size_t)(row0 + 8) * ldc + gcol]) =
                    packbf(acc[mi][ni][2], acc[mi][ni][3]);
            } else if (gcol < nSplit + DSTATE) {
                int ac = gcol - nSplit;
                *reinterpret_cast<float2*>(&Caux[(size_t)row0 * DSTATE + ac]) =
                    make_float2(acc[mi][ni][0], acc[mi][ni][1]);
                *reinterpret_cast<float2*>(&Caux[(size_t)(row0 + 8) * DSTATE + ac]) =
                    make_float2(acc[mi][ni][2], acc[mi][ni][3]);
            }
        }
}

// ---------------------------------------------------------------------------
// Wide-row fused GEMMs: BM=64, BN=256 (full row), BK=32, 512 threads.
// ---------------------------------------------------------------------------
#define FBM 64
#define FSA (FBM * ASTR)
#define FSB (256 * ASTR)

__device__ __forceinline__ void fused_mainloop(
    const bf16* __restrict__ A, int lda,
    const bf16* __restrict__ Bt, int ldb,
    int K, int rowBase, bf16* sm, float acc[8][4]) {

    bf16* sAb = sm;
    bf16* sBb = sm + 2 * FSA;

    const int tid  = threadIdx.x;
    const int lane = tid & 31;
    const int warp = tid >> 5;
    const int wm   = warp & 3;
    const int wn   = warp >> 2;
    const int mBase = wm * 16;
    const int nBase = wn * 64;

    const int t4 = lane >> 3;
    const int l7 = lane & 7;
    const int aRowL = (t4 & 1) * 8 + l7;
    const int aColL = (t4 >> 1) * 8;
    const int bRowL = (t4 >> 1) * 8 + l7;
    const int bColL = (t4 & 1) * 8;
    const uint32_t sA_u = (uint32_t)__cvta_generic_to_shared(sAb);
    const uint32_t sB_u = (uint32_t)__cvta_generic_to_shared(sBb);

    const bf16* Ab = A + (size_t)rowBase * lda;
    const int aRow = tid >> 2, aKc = tid & 3;
    const int b0Row = tid >> 2, b0Kc = tid & 3;
    const int b1Row = (tid + 512) >> 2, b1Kc = tid & 3;

    const int nIter = K / 32;
    {
        if (tid < 256)
            cp_async16(&sAb[aRow * ASTR + aKc * 8], Ab + (size_t)aRow * lda + aKc * 8);
        cp_async16(&sBb[b0Row * ASTR + b0Kc * 8], Bt + (size_t)b0Row * ldb + b0Kc * 8);
        cp_async16(&sBb[b1Row * ASTR + b1Kc * 8], Bt + (size_t)b1Row * ldb + b1Kc * 8);
        asm volatile("cp.async.commit_group;");
    }

    for (int it = 0; it < nIter; ++it) {
        if (it + 1 < nIter) {
            int st = (it + 1) & 1;
            int k0 = (it + 1) * 32;
            if (tid < 256)
                cp_async16(&sAb[st * FSA + aRow * ASTR + aKc * 8],
                           Ab + (size_t)aRow * lda + k0 + aKc * 8);
            cp_async16(&sBb[st * FSB + b0Row * ASTR + b0Kc * 8],
                       Bt + (size_t)b0Row * ldb + k0 + b0Kc * 8);
            cp_async16(&sBb[st * FSB + b1Row * ASTR + b1Kc * 8],
                       Bt + (size_t)b1Row * ldb + k0 + b1Kc * 8);
            asm volatile("cp.async.commit_group;");
            asm volatile("cp.async.wait_group 1;");
        } else {
            asm volatile("cp.async.wait_group 0;");
        }
        __syncthreads();

        const int buf = it & 1;
        const uint32_t aBuf = sA_u + buf * (FSA * 2);
        const uint32_t bBuf = sB_u + buf * (FSB * 2);

        #pragma unroll
        for (int ks = 0; ks < 2; ks++) {
            uint32_t af[4], bfr[8][2];
            uint32_t a_lds = aBuf + ((mBase + aRowL) * ASTR + ks * 16 + aColL) * 2;
            ldsm_x4(af[0], af[1], af[2], af[3], a_lds);
            #pragma unroll
            for (int p = 0; p < 4; p++) {
                uint32_t b_lds = bBuf +
                    ((nBase + p * 16 + bRowL) * ASTR + ks * 16 + bColL) * 2;
                ldsm_x4(bfr[2*p][0], bfr[2*p][1], bfr[2*p+1][0], bfr[2*p+1][1], b_lds);
            }
            #pragma unroll
            for (int ni = 0; ni < 8; ni++)
                mma16816(acc[ni], af, bfr[ni]);
        }
        __syncthreads();
    }
}

// out_proj GEMM + residual + RMSNorm -> px (fp32) and pxh (bf16)
__global__ void __launch_bounds__(512)
gemm_rms_kernel(const bf16* __restrict__ A,
                const bf16* __restrict__ Bt,
                float* __restrict__ x, bf16* __restrict__ xh,
                const float* __restrict__ nw) {
    extern __shared__ __align__(16) char dsm[];
    bf16* sm = (bf16*)dsm;
    float acc[8][4];
    #pragma unroll
    for (int ni = 0; ni < 8; ni++)
        #pragma unroll
        for (int c = 0; c < 4; c++) acc[ni][c] = 0.f;

    const int rowBase = blockIdx.x * FBM;
    fused_mainloop(A, DI, Bt, DI, DI, rowBase, sm, acc);

    const int tid  = threadIdx.x;
    const int lane = tid & 31;
    const int g    = lane >> 2;
    const int tg   = lane & 3;
    const int warp = tid >> 5;
    const int wm   = warp & 3;
    const int wn   = warp >> 2;
    const int r0   = wm * 16 + g;
    const int r1   = r0 + 8;
    const int t0   = rowBase + r0;
    const int t1   = rowBase + r1;

    float pA = 0.f, pB = 0.f;
    #pragma unroll
    for (int ni = 0; ni < 8; ni++) {
        int col = wn * 64 + ni * 8 + tg * 2;
        float2 x0 = *reinterpret_cast<const float2*>(&x[(size_t)t0 * DM + col]);
        float2 x1 = *reinterpret_cast<const float2*>(&x[(size_t)t1 * DM + col]);
        acc[ni][0] += x0.x; acc[ni][1] += x0.y;
        acc[ni][2] += x1.x; acc[ni][3] += x1.y;
        pA += acc[ni][0]*acc[ni][0] + acc[ni][1]*acc[ni][1];
        pB += acc[ni][2]*acc[ni][2] + acc[ni][3]*acc[ni][3];
    }
    pA += __shfl_xor_sync(0xffffffffu, pA, 1);
    pA += __shfl_xor_sync(0xffffffffu, pA, 2);
    pB += __shfl_xor_sync(0xffffffffu, pB, 1);
    pB += __shfl_xor_sync(0xffffffffu, pB, 2);

    float* sred = (float*)dsm;
    __syncthreads();
    if (tg == 0) { sred[r0 * 4 + wn] = pA; sred[r1 * 4 + wn] = pB; }
    __syncthreads();
    if (tid < 64) {
        float s = sred[tid*4] + sred[tid*4+1] + sred[tid*4+2] + sred[tid*4+3];
        sred[256 + tid] = rsqrtf(s * (1.f / DM) + RMS_EPS);
    }
    __syncthreads();
    float sc0 = sred[256 + r0];
    float sc1 = sred[256 + r1];

    #pragma unroll
    for (int ni = 0; ni < 8; ni++) {
        int col = wn * 64 + ni * 8 + tg * 2;
        float2 w = *reinterpret_cast<const float2*>(&nw[col]);
        float o0 = acc[ni][0] * sc0 * w.x, o1 = acc[ni][1] * sc0 * w.y;
        float o2 = acc[ni][2] * sc1 * w.x, o3 = acc[ni][3] * sc1 * w.y;
        *reinterpret_cast<float2*>(&x[(size_t)t0 * DM + col]) = make_float2(o0, o1);
        *reinterpret_cast<float2*>(&x[(size_t)t1 * DM + col]) = make_float2(o2, o3);
        *reinterpret_cast<uint32_t*>(&xh[(size_t)t0 * DM + col]) = packbf(o0, o1);
        *reinterpret_cast<uint32_t*>(&xh[(size_t)t1 * DM + col]) = packbf(o2, o3);
    }
}

// head GEMM + softmax entropy -> ent[TT]
__global__ void __launch_bounds__(512)
gemm_ent_kernel(const bf16* __restrict__ A,
                const bf16* __restrict__ Bt,
                float* __restrict__ ent) {
    extern __shared__ __align__(16) char dsm[];
    bf16* sm = (bf16*)dsm;
    float acc[8][4];
    #pragma unroll
    for (int ni = 0; ni < 8; ni++)
        #pragma unroll
        for (int c = 0; c < 4; c++) acc[ni][c] = 0.f;

    const int rowBase = blockIdx.x * FBM;
    fused_mainloop(A, DM, Bt, DM, DM, rowBase, sm, acc);

    const int tid  = threadIdx.x;
    const int lane = tid & 31;
    const int g    = lane >> 2;
    const int tg   = lane & 3;
    const int warp = tid >> 5;
    const int wm   = warp & 3;
    const int wn   = warp >> 2;
    const int r0   = wm * 16 + g;
    const int r1   = r0 + 8;

    float mA = -1e30f, mB = -1e30f;
    #pragma unroll
    for (int ni = 0; ni < 8; ni++) {
        mA = fmaxf(mA, fmaxf(acc[ni][0], acc[ni][1]));
        mB = fmaxf(mB, fmaxf(acc[ni][2], acc[ni][3]));
    }
    mA = fmaxf(mA, __shfl_xor_sync(0xffffffffu, mA, 1));
    mA = fmaxf(mA, __shfl_xor_sync(0xffffffffu, mA, 2));
    mB = fmaxf(mB, __shfl_xor_sync(0xffffffffu, mB, 1));
    mB = fmaxf(mB, __shfl_xor_sync(0xffffffffu, mB, 2));

    float* sred = (float*)dsm;
    __syncthreads();
    if (tg == 0) { sred[r0 * 4 + wn] = mA; sred[r1 * 4 + wn] = mB; }
    __syncthreads();
    if (tid < 64)
        sred[256 + tid] = fmaxf(fmaxf(sred[tid*4], sred[tid*4+1]),
                                fmaxf(sred[tid*4+2], sred[tid*4+3]));
    __syncthreads();
    float rm0 = sred[256 + r0];
    float rm1 = sred[256 + r1];
    __syncthreads();

    float zA = 0.f, sAc = 0.f, zB = 0.f, sBc = 0.f;
    #pragma unroll
    for (int ni = 0; ni < 8; ni++) {
        float d0 = acc[ni][0] - rm0, d1 = acc[ni][1] - rm0;
        float d2 = acc[ni][2] - rm1, d3 = acc[ni][3] - rm1;
        float e0 = __expf(d0), e1 = __expf(d1), e2 = __expf(d2), e3 = __expf(d3);
        zA += e0 + e1;  sAc += e0 * d0 + e1 * d1;
        zB += e2 + e3;  sBc += e2 * d2 + e3 * d3;
    }
    zA  += __shfl_xor_sync(0xffffffffu, zA, 1);
    zA  += __shfl_xor_sync(0xffffffffu, zA, 2);
    sAc += __shfl_xor_sync(0xffffffffu, sAc, 1);
    sAc += __shfl_xor_sync(0xffffffffu, sAc, 2);
    zB  += __shfl_xor_sync(0xffffffffu, zB, 1);
    zB  += __shfl_xor_sync(0xffffffffu, zB, 2);
    sBc += __shfl_xor_sync(0xffffffffu, sBc, 1);
    sBc += __shfl_xor_sync(0xffffffffu, sBc, 2);

    if (tg == 0) {
        sred[r0 * 4 + wn] = zA;        sred[r1 * 4 + wn] = zB;
        sred[320 + r0 * 4 + wn] = sAc; sred[320 + r1 * 4 + wn] = sBc;
    }
    __syncthreads();
    if (tid < 64) {
        float Z = sred[tid*4] + sred[tid*4+1] + sred[tid*4+2] + sred[tid*4+3];
        float S = sred[320+tid*4] + sred[320+tid*4+1] + sred[320+tid*4+2] + sred[320+tid*4+3];
        ent[rowBase + tid] = (__logf(Z) - __fdividef(S, Z)) * (1.f / LOG_VOCAB_F);
    }
}

// ---------------------------------------------------------------------------
// Causal depthwise conv + bias + silu — register sliding window, 4 ch/thread
// ---------------------------------------------------------------------------
#define TCONV 16
__global__ void __launch_bounds__(256)
conv_silu_kernel(const bf16* __restrict__ xinzh,
                 const float* __restrict__ cw,
                 const float* __restrict__ cb,
                 bf16* __restrict__ xch) {
    const int tid = threadIdx.x;
    const int vec = tid & 127;
    const int tgrp = tid >> 7;
    const int dv = vec * 4;

    const int tokBlk = blockIdx.x;
    const int b = tokBlk / (SS / 32);
    const int sBase = (tokBlk % (SS / 32)) * 32 + tgrp * TCONV;

    float w[4][DCONV], bias[4];
    {
        float4 bv = *reinterpret_cast<const float4*>(&cb[dv]);
        bias[0] = bv.x; bias[1] = bv.y; bias[2] = bv.z; bias[3] = bv.w;
        #pragma unroll
        for (int j = 0; j < 4; j++) {
            float4 wv = *reinterpret_cast<const float4*>(&cw[(dv + j) * DCONV]);
            w[j][0] = wv.x; w[j][1] = wv.y; w[j][2] = wv.z; w[j][3] = wv.w;
        }
    }

    float p3[4], p2[4], p1[4];
    #pragma unroll
    for (int j = 0; j < 4; j++) { p3[j] = 0.f; p2[j] = 0.f; p1[j] = 0.f; }

    const bf16* rowBase = xinzh + (size_t)b * SS * (2 * DI) + dv;
    #define LOADROW(dst, s) { \
        uint2 raw = *reinterpret_cast<const uint2*>(rowBase + (size_t)(s) * (2 * DI)); \
        const __nv_bfloat162* h2 = reinterpret_cast<const __nv_bfloat162*>(&raw); \
        _Pragma("unroll") \
        for (int j = 0; j < 2; j++) { \
            float2 f = __bfloat1622float2(h2[j]); \
            dst[2*j] = f.x; dst[2*j+1] = f.y; } }

    if (sBase >= 3) { LOADROW(p3, sBase - 3); }
    if (sBase >= 2) { LOADROW(p2, sBase - 2); }
    if (sBase >= 1) { LOADROW(p1, sBase - 1); }

    bf16* outBase = xch + (size_t)b * SS * DI + dv;

    #pragma unroll
    for (int i = 0; i < TCONV; i++) {
        int s = sBase + i;
        float cur[4];
        LOADROW(cur, s);

        uint2 outv;
        uint32_t* o = reinterpret_cast<uint32_t*>(&outv);
        #pragma unroll
        for (int j = 0; j < 2; j++) {
            float a0 = bias[2*j], a1 = bias[2*j+1];
            a0 = fmaf(w[2*j][0],   p3[2*j],   a0);
            a1 = fmaf(w[2*j+1][0], p3[2*j+1], a1);
            a0 = fmaf(w[2*j][1],   p2[2*j],   a0);
            a1 = fmaf(w[2*j+1][1], p2[2*j+1], a1);
            a0 = fmaf(w[2*j][2],   p1[2*j],   a0);
            a1 = fmaf(w[2*j+1][2], p1[2*j+1], a1);
            a0 = fmaf(w[2*j][3],   cur[2*j],   a0);
            a1 = fmaf(w[2*j+1][3], cur[2*j+1], a1);
            float v0 = __fdividef(a0, 1.f + __expf(-a0));
            float v1 = __fdividef(a1, 1.f + __expf(-a1));
            o[j] = packbf(v0, v1);
        }
        *reinterpret_cast<uint2*>(outBase + (size_t)s * DI) = outv;

        #pragma unroll
        for (int j = 0; j < 4; j++) { p3[j] = p2[j]; p2[j] = p1[j]; p1[j] = cur[j]; }
    }
    #undef LOADROW
}

// ---------------------------------------------------------------------------
// Fused Mamba pointwise core (exp2-based MUFU path)
// ---------------------------------------------------------------------------
#define EW_TOKS 8
__global__ void mamba_ew_kernel(const bf16* __restrict__ dth,
                                const bf16* __restrict__ xch,
                                const bf16* __restrict__ xinzh,
                                const float* __restrict__ Bmat,
                                const float* __restrict__ Alog,
                                const float* __restrict__ dtb,
                                const float* __restrict__ Dp,
                                bf16* __restrict__ uh) {
    __shared__ float negAT[DSTATE][DI];   // pre-scaled by log2(e)
    __shared__ float sdtb[DI];
    __shared__ float sD[DI];
    __shared__ float sB[DSTATE];

    const int tid = threadIdx.x;
    for (int i = tid; i < DI * DSTATE; i += 256) {
        int d = i / DSTATE, n = i % DSTATE;
        negAT[n][d] = -__expf(Alog[i]) * LOG2E_F;
    }
    for (int i = tid; i < DI; i += 256) { sdtb[i] = dtb[i]; sD[i] = Dp[i]; }
    __syncthreads();

    for (int tok = 0; tok < EW_TOKS; tok++) {
        int t = blockIdx.x * EW_TOKS + tok;
        if (tid < DSTATE) sB[tid] = Bmat[t * DSTATE + tid];
        __syncthreads();

        #pragma unroll
        for (int rep = 0; rep < 2; rep++) {
            int d = tid + rep * 256;
            float v   = __bfloat162float(dth[(size_t)t * DI + d]) + sdtb[d];
            float dtv = fmaxf(v, 0.f) + __logf(1.f + __expf(-fabsf(v)));
            float xcv = __bfloat162float(xch[(size_t)t * DI + d]);
            float accn = 0.f;
            #pragma unroll
            for (int n = 0; n < DSTATE; n++)
                accn = fmaf(exp2f(negAT[n][d] * dtv), sB[n], accn);
            float yv = dtv * xcv * accn + sD[d] * xcv;
            float zv = __bfloat162float(xinzh[(size_t)t * (2 * DI) + DI + d]);
            uh[(size_t)t * DI + d] =
                __float2bfloat16_rn(yv * __fdividef(zv, 1.f + __expf(-zv)));
        }
        __syncthreads();
    }
}

// ---------------------------------------------------------------------------
// Parallel boundary computation (scan).
// ---------------------------------------------------------------------------
__global__ void boundary_kernel(const float* __restrict__ ent,
                                int* __restrict__ pstart,
                                int* __restrict__ np,
                                float* __restrict__ out_b2p) {
    __shared__ int sh[256];
    int b = blockIdx.x;
    int tid = threadIdx.x;
    int base = tid * 8;

    float e[8];
    #pragma unroll
    for (int i = 0; i < 8; i++) e[i] = ent[b * SS + base + i];

    int hard[8];
    int lasth = -1;
    #pragma unroll
    for (int i = 0; i < 8; i++) {
        hard[i] = (base + i == 0) || (e[i] > 0.5f);
        if (hard[i]) lasth = base + i;
    }

    sh[tid] = lasth;
    __syncthreads();
    for (int off = 1; off < 256; off <<= 1) {
        int u = sh[tid];
        int w = (tid >= off) ? sh[tid - off] : -1;
        __syncthreads();
        sh[tid] = max(u, w);
        __syncthreads();
    }
    int ph = (tid > 0) ? sh[tid - 1] : -1;

    int bnd[8];
    int cnt = 0;
    #pragma unroll
    for (int i = 0; i < 8; i++) {
        int s = base + i;
        if (hard[i]) ph = s;
        bnd[i] = hard[i] || (((s - ph) & 7) == 0);
        cnt += bnd[i];
    }

    __syncthreads();
    sh[tid] = cnt;
    __syncthreads();
    for (int off = 1; off < 256; off <<= 1) {
        int u = sh[tid];
        int w = (tid >= off) ? sh[tid - off] : 0;
        __syncthreads();
        sh[tid] = u + w;
        __syncthreads();
    }
    int pref = (tid > 0) ? sh[tid - 1] : 0;

    int c = 0;
    #pragma unroll
    for (int i = 0; i < 8; i++) {
        int s = base + i;
        c += bnd[i];
        int p = pref + c - 1;
        out_b2p[b * SS + s] = (float)p;
        if (bnd[i]) pstart[b * SS + p] = s;
    }
    if (tid == 255) np[b] = sh[255];
}

// ---------------------------------------------------------------------------
// Patch mean pooling
// ---------------------------------------------------------------------------
__global__ void pool_kernel(const float* __restrict__ be,
                            const int* __restrict__ pstart,
                            const int* __restrict__ np,
                            float* __restrict__ out_emb,
                            float* __restrict__ out_len) {
    int blk = blockIdx.x;
    int b = blk / SS;
    int p = blk - b * SS;
    int d = threadIdx.x;
    int npb = np[b];

    if (p < npb) {
        int s0 = pstart[b * SS + p];
        int s1 = (p + 1 < npb) ? pstart[b * SS + p + 1] : SS;
        float sum = 0.f;
        for (int s = s0; s < s1; s++)
            sum += be[(size_t)(b * SS + s) * DM + d];
        out_emb[(size_t)blk * DM + d] = sum / (float)(s1 - s0);
        if (d == 0) out_len[blk] = (float)(s1 - s0);
    } else {
        out_emb[(size_t)blk * DM + d] = 0.f;
        if (d == 0) out_len[blk] = 0.f;
    }
}

// ---------------------------------------------------------------------------
// Launch
// ---------------------------------------------------------------------------
#define FUSED_SMEM 51200

extern "C" void kernel_launch(void* const* d_in, const int* in_sizes, int n_in,
                              void* d_out, int out_size) {
    const int*   bytes = (const int*)  d_in[0];
    const float* be    = (const float*)d_in[1];
    const float* embW  = (const float*)d_in[2];
    const float* inW   = (const float*)d_in[3];
    const float* cw    = (const float*)d_in[4];
    const float* cb    = (const float*)d_in[5];
    const float* xpW   = (const float*)d_in[6];
    const float* dtW   = (const float*)d_in[7];
    const float* dtb   = (const float*)d_in[8];
    const float* Alog  = (const float*)d_in[9];
    const float* Dp    = (const float*)d_in[10];
    const float* outW  = (const float*)d_in[11];
    const float* nw    = (const float*)d_in[12];
    const float* headW = (const float*)d_in[13];
    float* out = (float*)d_out;

    static float *px=nullptr, *pB, *pent;
    static bf16 *pxh, *pxinzh, *pxch, *pdth, *puh, *pwbf, *pwdtm;
    static int *ppstart, *pnp;
    if (!px) {
        cudaGetSymbolAddress((void**)&px,     g_x);
        cudaGetSymbolAddress((void**)&pxh,    g_xh);
        cudaGetSymbolAddress((void**)&pxinzh, g_xinzh);
        cudaGetSymbolAddress((void**)&pxch,   g_xch);
        cudaGetSymbolAddress((void**)&pdth,   g_dth);
        cudaGetSymbolAddress((void**)&pB,     g_Bm);
        cudaGetSymbolAddress((void**)&puh,    g_uh);
        cudaGetSymbolAddress((void**)&pent,   g_ent);
        cudaGetSymbolAddress((void**)&pwbf,   g_wbf);
        cudaGetSymbolAddress((void**)&pwdtm,  g_wdtm);
        cudaGetSymbolAddress((void**)&ppstart,g_pstart);
        cudaGetSymbolAddress((void**)&pnp,    g_np);
        cudaFuncSetAttribute(gemm_rms_kernel,
            cudaFuncAttributeMaxDynamicSharedMemorySize, FUSED_SMEM);
        cudaFuncSetAttribute(gemm_ent_kernel,
            cudaFuncAttributeMaxDynamicSharedMemorySize, FUSED_SMEM);
        cudaFuncSetAttribute(mma_gemm128_kernel,
            cudaFuncAttributeMaxDynamicSharedMemorySize, G128_SMEM);
    }

    // 0) weight prep + embedding (single launch)
    prep_kernel<<<1384 + TT * DM / 1024, 256>>>(
        inW, dtW, outW, headW, xpW, bytes, embW, pwbf, pwdtm, px, pxh);

    // 1) two mamba blocks
    for (int l = 0; l < 2; l++) {
        // x @ in_proj -> xinz bf16  (N=1024, K=256)
        mma_gemm128_kernel<<<dim3(1024/GBN, TT/GBM), 256, G128_SMEM>>>(
            pxh, DM, pwbf + WOFF_IN(l), DM, pxinzh, 2 * DI, nullptr, 4096, DM);
        // depthwise conv + silu
        conv_silu_kernel<<<TT / 32, 256>>>(
            pxinzh, cw + (size_t)l * DI * DCONV, cb + (size_t)l * DI, pxch);
        // xc @ [dt_w | x_proj_B | pad] -> dt bf16 + Bmat fp32  (N=640, K=512)
        mma_gemm128_kernel<<<dim3(NMERGE/GBN, TT/GBM), 256, G128_SMEM>>>(
            pxch, DI, pwdtm + (size_t)l * NMERGE * 512, DI,
            pdth, DI, pB, 512, DI);
        // fused pointwise core
        mamba_ew_kernel<<<TT / EW_TOKS, 256>>>(
            pdth, pxch, pxinzh, pB,
            Alog + (size_t)l * DI * DSTATE, dtb + (size_t)l * DI,
            Dp + (size_t)l * DI, puh);
        // u @ out_w + residual + rmsnorm (fused)
        gemm_rms_kernel<<<TT / FBM, 512, FUSED_SMEM>>>(
            puh, pwbf + WOFF_OUT(l), px, pxh, nw + (size_t)l * DM);
    }

    // 2) head + entropy (fused)
    gemm_ent_kernel<<<TT / FBM, 512, FUSED_SMEM>>>(pxh, pwbf + WOFF_HEAD, pent);

    // 3) boundaries (parallel scan)
    boundary_kernel<<<BB, 256>>>(pent, ppstart, pnp, out + (size_t)TT * DM + TT);

    // 4) patch pooling
    pool_kernel<<<BB * SS, 256>>>(be, ppstart, pnp, out, out + (size_t)TT * DM);
}

// round 17
// speedup vs baseline: 1.0243x; 1.0205x over previous
#include <cuda_runtime.h>
#include <cuda_bf16.h>
#include <math.h>
#include <stdint.h>

// ---------------------------------------------------------------------------
// Problem constants
// ---------------------------------------------------------------------------
#define BB     8
#define SS     2048
#define TT     (BB*SS)
#define DM     256
#define DI     512
#define DSTATE 16
#define DCONV  4
#define NVOCAB 256
#define LOG_VOCAB_F 5.5451774444795623f
#define RMS_EPS 1.1920928955078125e-7f
#define LOG2E_F 1.4426950408889634f

typedef __nv_bfloat16 bf16;

// ---------------------------------------------------------------------------
// Scratch
// ---------------------------------------------------------------------------
__device__ float g_x    [TT * DM];        // residual stream fp32
__device__ bf16  g_xh   [TT * DM];        // residual stream bf16
__device__ bf16  g_xinzh[TT * 2 * DI];    // in_proj out (x_in | z) bf16
__device__ bf16  g_xch  [TT * DI];        // conv+silu out bf16
__device__ bf16  g_dth  [TT * DI];        // dt pre-activation bf16
__device__ float g_Bm   [TT * DSTATE];    // B matrix fp32
__device__ bf16  g_uh   [TT * DI];        // gated y bf16
__device__ float g_ent  [TT];
__device__ int   g_pstart[BB * SS];
__device__ int   g_np    [BB];

// bf16 transposed weights [N,K] row-major, packed
#define WOFF_IN(l)   ((size_t)(l) * 1024 * 256)
#define WOFF_OUT(l)  (524288u + (size_t)(l) * 256 * 512)
#define WOFF_HEAD    (786432u)
__device__ bf16 g_wbf[851968];
// merged dt + x_proj(B half) weights: [576][512] per layer
// rows 0..511 = dtW^T, 512..527 = x_proj B^T, 528..575 zero pad (9 x 64 tiles)
#define NMERGE 576
__device__ bf16 g_wdtm[2 * NMERGE * 512];

// ---------------------------------------------------------------------------
// Weight prep + embedding, ALL in one launch.
//  blk 0..511    : in_proj   blk 512..1023 : dt      blk 1024..1279: out
//  blk 1280..1343: head      blk 1344..1375: x_proj  blk 1376..1383: zero pad
//  blk 1384..5479: embedding
// ---------------------------------------------------------------------------
__global__ void prep_kernel(const float* __restrict__ inW,
                            const float* __restrict__ dtW,
                            const float* __restrict__ outW,
                            const float* __restrict__ headW,
                            const float* __restrict__ xpW,
                            const int* __restrict__ bytes,
                            const float* __restrict__ embW,
                            bf16* __restrict__ wout,
                            bf16* __restrict__ wdtm,
                            float* __restrict__ x,
                            bf16* __restrict__ xh) {
    __shared__ float tile[32][33];
    int blk = blockIdx.x;
    int tx = threadIdx.x & 31, ty = threadIdx.x >> 5;

    if (blk >= 1384) {               // embedding: 4096 blocks, 4 elems/thread
        int vid = (blk - 1384) * 256 + threadIdx.x;
        int t = vid >> 6;
        int d4 = (vid & 63) * 4;
        float4 v = *reinterpret_cast<const float4*>(&embW[bytes[t] * DM + d4]);
        *reinterpret_cast<float4*>(&x[(size_t)t * DM + d4]) = v;
        __nv_bfloat162 h0 = __float22bfloat162_rn(make_float2(v.x, v.y));
        __nv_bfloat162 h1 = __float22bfloat162_rn(make_float2(v.z, v.w));
        uint32_t u0 = *reinterpret_cast<uint32_t*>(&h0);
        uint32_t u1 = *reinterpret_cast<uint32_t*>(&h1);
        *reinterpret_cast<uint2*>(&xh[(size_t)t * DM + d4]) = make_uint2(u0, u1);
        return;
    }
    if (blk >= 1376) {               // zero-fill pad rows 528..575 (48 rows/layer)
        int idx = blk - 1376;        // 0..7
        int l = idx >> 2, part = idx & 3;
        bf16* O = wdtm + (size_t)l * NMERGE * 512 + (528 + part * 12) * 512;
        for (int i = threadIdx.x; i < 12 * 512; i += 256) O[i] = __float2bfloat16_rn(0.f);
        return;
    }
    if (blk >= 1344) {               // x_proj B half transpose -> rows 512..527
        int idx = blk - 1344;
        int l = idx >> 4, t = idx & 15;
        const float* W = xpW + (size_t)l * DI * 2 * DSTATE;
        bf16* O = wdtm + (size_t)l * NMERGE * 512;
        int kb = t * 32;
        #pragma unroll
        for (int r = ty; r < 32; r += 8)
            tile[r][tx] = W[(size_t)(kb + r) * 32 + tx];
        __syncthreads();
        for (int r = ty; r < 16; r += 8)
            O[(size_t)(512 + r) * 512 + kb + tx] = __float2bfloat16_rn(tile[tx][r]);
        return;
    }

    const float* W; bf16* O; int K, N, t;
    if (blk < 512)       { int l = blk >> 8;        t = blk & 255;        W = inW  + (size_t)l*DM*2*DI; O = wout + WOFF_IN(l);            K = DM; N = 2*DI; }
    else if (blk < 1024) { int l = (blk-512) >> 8;  t = blk & 255;        W = dtW  + (size_t)l*DI*DI;   O = wdtm + (size_t)l*NMERGE*512;  K = DI; N = DI; }
    else if (blk < 1280) { int l = (blk-1024) >> 7; t = (blk-1024) & 127; W = outW + (size_t)l*DI*DM;   O = wout + WOFF_OUT(l);           K = DI; N = DM; }
    else                 { t = blk - 1280;          W = headW;            O = wout + WOFF_HEAD;         K = DM; N = NVOCAB; }
    int ncols = N >> 5;
    int nb = (t % ncols) * 32, kb = (t / ncols) * 32;
    #pragma unroll
    for (int r = ty; r < 32; r += 8)
        tile[r][tx] = W[(size_t)(kb + r) * N + nb + tx];
    __syncthreads();
    #pragma unroll
    for (int r = ty; r < 32; r += 8)
        O[(size_t)(nb + r) * K + kb + tx] = __float2bfloat16_rn(tile[tx][r]);
}

// ---------------------------------------------------------------------------
// mma helpers
// ---------------------------------------------------------------------------
__device__ __forceinline__ void cp_async16(void* smem, const void* gmem) {
    uint32_t s = (uint32_t)__cvta_generic_to_shared(smem);
    asm volatile("cp.async.cg.shared.global [%0], [%1], 16;" :: "r"(s), "l"(gmem));
}
__device__ __forceinline__ void ldsm_x4(uint32_t& r0, uint32_t& r1,
                                        uint32_t& r2, uint32_t& r3, uint32_t saddr) {
    asm volatile("ldmatrix.sync.aligned.m8n8.x4.shared.b16 {%0,%1,%2,%3}, [%4];"
        : "=r"(r0), "=r"(r1), "=r"(r2), "=r"(r3) : "r"(saddr));
}
__device__ __forceinline__ void mma16816(float* c, const uint32_t* a, const uint32_t* b) {
    asm volatile(
        "mma.sync.aligned.m16n8k16.row.col.f32.bf16.bf16.f32 "
        "{%0,%1,%2,%3},{%4,%5,%6,%7},{%8,%9},{%0,%1,%2,%3};"
        : "+f"(c[0]), "+f"(c[1]), "+f"(c[2]), "+f"(c[3])
        : "r"(a[0]), "r"(a[1]), "r"(a[2]), "r"(a[3]), "r"(b[0]), "r"(b[1]));
}
__device__ __forceinline__ uint32_t packbf(float a, float b) {
    __nv_bfloat162 h = __float22bfloat162_rn(make_float2(a, b));
    return *reinterpret_cast<uint32_t*>(&h);
}

#define ASTR 40

// ---------------------------------------------------------------------------
// 128x64x32 bf16 tensor-core GEMM, 256 threads (4x2 warps, 32x32 each),
// 3-stage cp.async pipeline, ONE __syncthreads per K-iter,
// __launch_bounds__(256,3) -> 3 blocks/SM. Optional fp32 aux col split:
//   cols < nSplit -> bf16 C;  nSplit..nSplit+15 -> fp32 Caux;  rest dropped.
// ---------------------------------------------------------------------------
#define GBM 128
#define GBN 64
#define STG_A (GBM * ASTR)
#define STG_B (GBN * ASTR)
#define STG_T (STG_A + STG_B)
#define G128_SMEM (3 * STG_T * 2)     // 46080 bytes

__global__ void __launch_bounds__(256, 3)
mma_gemm128_kernel(const bf16* __restrict__ A, int lda,
                   const bf16* __restrict__ Bt, int ldb,
                   bf16* __restrict__ C, int ldc,
                   float* __restrict__ Caux, int nSplit,
                   int K) {
    extern __shared__ __align__(16) bf16 smem[];   // [3][STG_T]: A then B

    const int tid  = threadIdx.x;
    const int lane = tid & 31;
    const int g    = lane >> 2;
    const int tg   = lane & 3;
    const int warp = tid >> 5;
    const int wm   = warp & 3;
    const int wn   = warp >> 2;
    const int mBase = wm * 32;
    const int nBase = wn * 32;
    const int rowBase = blockIdx.y * GBM;
    const int colBase = blockIdx.x * GBN;

    const int t4 = lane >> 3;
    const int l7 = lane & 7;
    const int aRowL = (t4 & 1) * 8 + l7;
    const int aColL = (t4 >> 1) * 8;
    const int bRowL = (t4 >> 1) * 8 + l7;
    const int bColL = (t4 & 1) * 8;
    const uint32_t sm_u = (uint32_t)__cvta_generic_to_shared(smem);

    const int cRow = tid >> 2, cKc = tid & 3;
    const bf16* Ab = A + (size_t)rowBase * lda;
    const bf16* Bb = Bt + (size_t)colBase * ldb;

    float acc[2][4][4];
    #pragma unroll
    for (int mi = 0; mi < 2; mi++)
        #pragma unroll
        for (int ni = 0; ni < 4; ni++)
            #pragma unroll
            for (int c = 0; c < 4; c++) acc[mi][ni][c] = 0.f;

    const int nIter = K / 32;

    #pragma unroll
    for (int s = 0; s < 2; s++) {
        bf16* sA = smem + s * STG_T;
        bf16* sB = sA + STG_A;
        int k0 = s * 32;
        cp_async16(&sA[cRow * ASTR + cKc * 8],        Ab + (size_t)cRow * lda + k0 + cKc * 8);
        cp_async16(&sA[(cRow + 64) * ASTR + cKc * 8], Ab + (size_t)(cRow + 64) * lda + k0 + cKc * 8);
        cp_async16(&sB[cRow * ASTR + cKc * 8],        Bb + (size_t)cRow * ldb + k0 + cKc * 8);
        asm volatile("cp.async.commit_group;");
    }

    for (int it = 0; it < nIter; ++it) {
        asm volatile("cp.async.wait_group 1;");
        __syncthreads();

        int pf = it + 2;
        if (pf < nIter) {
            int st = pf % 3;
            bf16* sA = smem + st * STG_T;
            bf16* sB = sA + STG_A;
            int k0 = pf * 32;
            cp_async16(&sA[cRow * ASTR + cKc * 8],        Ab + (size_t)cRow * lda + k0 + cKc * 8);
            cp_async16(&sA[(cRow + 64) * ASTR + cKc * 8], Ab + (size_t)(cRow + 64) * lda + k0 + cKc * 8);
            cp_async16(&sB[cRow * ASTR + cKc * 8],        Bb + (size_t)cRow * ldb + k0 + cKc * 8);
        }
        asm volatile("cp.async.commit_group;");

        const int buf = it % 3;
        const uint32_t aBuf = sm_u + buf * (STG_T * 2);
        const uint32_t bBuf = aBuf + STG_A * 2;

        #pragma unroll
        for (int ks = 0; ks < 2; ks++) {
            uint32_t af[2][4], bfr[4][2];
            #pragma unroll
            for (int mi = 0; mi < 2; mi++) {
                uint32_t a_lds = aBuf +
                    ((mBase + mi * 16 + aRowL) * ASTR + ks * 16 + aColL) * 2;
                ldsm_x4(af[mi][0], af[mi][1], af[mi][2], af[mi][3], a_lds);
            }
            #pragma unroll
            for (int p = 0; p < 2; p++) {
                uint32_t b_lds = bBuf +
                    ((nBase + p * 16 + bRowL) * ASTR + ks * 16 + bColL) * 2;
                ldsm_x4(bfr[2*p][0], bfr[2*p][1], bfr[2*p+1][0], bfr[2*p+1][1], b_lds);
            }
            #pragma unroll
            for (int mi = 0; mi < 2; mi++)
                #pragma unroll
                for (int ni = 0; ni < 4; ni++)
                    mma16816(acc[mi][ni], af[mi], bfr[ni]);
        }
    }

    #pragma unroll
    for (int mi = 0; mi < 2; mi++)
        #pragma unroll
        for (int ni = 0; ni < 4; ni++) {
            int row0 = rowBase + mBase + mi * 16 + g;
            int gcol = colBase + nBase + ni * 8 + tg * 2;
            if (gcol < nSplit) {
                *reinterpret_cast<uint32_t*>(&C[(size_t)row0 * ldc + gcol]) =
                    packbf(acc[mi][ni][0], acc[mi][ni][1]);
                *reinterpret_cast<uint32_t*>(&C[(size_t)(row0 + 8) * ldc + gcol]) =
                    packbf(acc[mi][ni][2], acc[mi][ni][3]);
            } else if (gcol < nSplit + DSTATE) {
                int ac = gcol - nSplit;
                *reinterpret_cast<float2*>(&Caux[(size_t)row0 * DSTATE + ac]) =
                    make_float2(acc[mi][ni][0], acc[mi][ni][1]);
                *reinterpret_cast<float2*>(&Caux[(size_t)(row0 + 8) * DSTATE + ac]) =
                    make_float2(acc[mi][ni][2], acc[mi][ni][3]);
            }
        }
}

// ---------------------------------------------------------------------------
// Wide-row fused GEMMs: BM=64, BN=256 (full row), BK=32, 512 threads.
// ---------------------------------------------------------------------------
#define FBM 64
#define FSA (FBM * ASTR)
#define FSB (256 * ASTR)

__device__ __forceinline__ void fused_mainloop(
    const bf16* __restrict__ A, int lda,
    const bf16* __restrict__ Bt, int ldb,
    int K, int rowBase, bf16* sm, float acc[8][4]) {

    bf16* sAb = sm;
    bf16* sBb = sm + 2 * FSA;

    const int tid  = threadIdx.x;
    const int lane = tid & 31;
    const int warp = tid >> 5;
    const int wm   = warp & 3;
    const int wn   = warp >> 2;
    const int mBase = wm * 16;
    const int nBase = wn * 64;

    const int t4 = lane >> 3;
    const int l7 = lane & 7;
    const int aRowL = (t4 & 1) * 8 + l7;
    const int aColL = (t4 >> 1) * 8;
    const int bRowL = (t4 >> 1) * 8 + l7;
    const int bColL = (t4 & 1) * 8;
    const uint32_t sA_u = (uint32_t)__cvta_generic_to_shared(sAb);
    const uint32_t sB_u = (uint32_t)__cvta_generic_to_shared(sBb);

    const bf16* Ab = A + (size_t)rowBase * lda;
    const int aRow = tid >> 2, aKc = tid & 3;
    const int b0Row = tid >> 2, b0Kc = tid & 3;
    const int b1Row = (tid + 512) >> 2, b1Kc = tid & 3;

    const int nIter = K / 32;
    {
        if (tid < 256)
            cp_async16(&sAb[aRow * ASTR + aKc * 8], Ab + (size_t)aRow * lda + aKc * 8);
        cp_async16(&sBb[b0Row * ASTR + b0Kc * 8], Bt + (size_t)b0Row * ldb + b0Kc * 8);
        cp_async16(&sBb[b1Row * ASTR + b1Kc * 8], Bt + (size_t)b1Row * ldb + b1Kc * 8);
        asm volatile("cp.async.commit_group;");
    }

    for (int it = 0; it < nIter; ++it) {
        if (it + 1 < nIter) {
            int st = (it + 1) & 1;
            int k0 = (it + 1) * 32;
            if (tid < 256)
                cp_async16(&sAb[st * FSA + aRow * ASTR + aKc * 8],
                           Ab + (size_t)aRow * lda + k0 + aKc * 8);
            cp_async16(&sBb[st * FSB + b0Row * ASTR + b0Kc * 8],
                       Bt + (size_t)b0Row * ldb + k0 + b0Kc * 8);
            cp_async16(&sBb[st * FSB + b1Row * ASTR + b1Kc * 8],
                       Bt + (size_t)b1Row * ldb + k0 + b1Kc * 8);
            asm volatile("cp.async.commit_group;");
            asm volatile("cp.async.wait_group 1;");
        } else {
            asm volatile("cp.async.wait_group 0;");
        }
        __syncthreads();

        const int buf = it & 1;
        const uint32_t aBuf = sA_u + buf * (FSA * 2);
        const uint32_t bBuf = sB_u + buf * (FSB * 2);

        #pragma unroll
        for (int ks = 0; ks < 2; ks++) {
            uint32_t af[4], bfr[8][2];
            uint32_t a_lds = aBuf + ((mBase + aRowL) * ASTR + ks * 16 + aColL) * 2;
            ldsm_x4(af[0], af[1], af[2], af[3], a_lds);
            #pragma unroll
            for (int p = 0; p < 4; p++) {
                uint32_t b_lds = bBuf +
                    ((nBase + p * 16 + bRowL) * ASTR + ks * 16 + bColL) * 2;
                ldsm_x4(bfr[2*p][0], bfr[2*p][1], bfr[2*p+1][0], bfr[2*p+1][1], b_lds);
            }
            #pragma unroll
            for (int ni = 0; ni < 8; ni++)
                mma16816(acc[ni], af, bfr[ni]);
        }
        __syncthreads();
    }
}

// out_proj GEMM + residual + RMSNorm -> px (fp32) and pxh (bf16)
__global__ void __launch_bounds__(512)
gemm_rms_kernel(const bf16* __restrict__ A,
                const bf16* __restrict__ Bt,
                float* __restrict__ x, bf16* __restrict__ xh,
                const float* __restrict__ nw) {
    extern __shared__ __align__(16) char dsm[];
    bf16* sm = (bf16*)dsm;
    float acc[8][4];
    #pragma unroll
    for (int ni = 0; ni < 8; ni++)
        #pragma unroll
        for (int c = 0; c < 4; c++) acc[ni][c] = 0.f;

    const int rowBase = blockIdx.x * FBM;
    fused_mainloop(A, DI, Bt, DI, DI, rowBase, sm, acc);

    const int tid  = threadIdx.x;
    const int lane = tid & 31;
    const int g    = lane >> 2;
    const int tg   = lane & 3;
    const int warp = tid >> 5;
    const int wm   = warp & 3;
    const int wn   = warp >> 2;
    const int r0   = wm * 16 + g;
    const int r1   = r0 + 8;
    const int t0   = rowBase + r0;
    const int t1   = rowBase + r1;

    float pA = 0.f, pB = 0.f;
    #pragma unroll
    for (int ni = 0; ni < 8; ni++) {
        int col = wn * 64 + ni * 8 + tg * 2;
        float2 x0 = *reinterpret_cast<const float2*>(&x[(size_t)t0 * DM + col]);
        float2 x1 = *reinterpret_cast<const float2*>(&x[(size_t)t1 * DM + col]);
        acc[ni][0] += x0.x; acc[ni][1] += x0.y;
        acc[ni][2] += x1.x; acc[ni][3] += x1.y;
        pA += acc[ni][0]*acc[ni][0] + acc[ni][1]*acc[ni][1];
        pB += acc[ni][2]*acc[ni][2] + acc[ni][3]*acc[ni][3];
    }
    pA += __shfl_xor_sync(0xffffffffu, pA, 1);
    pA += __shfl_xor_sync(0xffffffffu, pA, 2);
    pB += __shfl_xor_sync(0xffffffffu, pB, 1);
    pB += __shfl_xor_sync(0xffffffffu, pB, 2);

    float* sred = (float*)dsm;
    __syncthreads();
    if (tg == 0) { sred[r0 * 4 + wn] = pA; sred[r1 * 4 + wn] = pB; }
    __syncthreads();
    if (tid < 64) {
        float s = sred[tid*4] + sred[tid*4+1] + sred[tid*4+2] + sred[tid*4+3];
        sred[256 + tid] = rsqrtf(s * (1.f / DM) + RMS_EPS);
    }
    __syncthreads();
    float sc0 = sred[256 + r0];
    float sc1 = sred[256 + r1];

    #pragma unroll
    for (int ni = 0; ni < 8; ni++) {
        int col = wn * 64 + ni * 8 + tg * 2;
        float2 w = *reinterpret_cast<const float2*>(&nw[col]);
        float o0 = acc[ni][0] * sc0 * w.x, o1 = acc[ni][1] * sc0 * w.y;
        float o2 = acc[ni][2] * sc1 * w.x, o3 = acc[ni][3] * sc1 * w.y;
        *reinterpret_cast<float2*>(&x[(size_t)t0 * DM + col]) = make_float2(o0, o1);
        *reinterpret_cast<float2*>(&x[(size_t)t1 * DM + col]) = make_float2(o2, o3);
        *reinterpret_cast<uint32_t*>(&xh[(size_t)t0 * DM + col]) = packbf(o0, o1);
        *reinterpret_cast<uint32_t*>(&xh[(size_t)t1 * DM + col]) = packbf(o2, o3);
    }
}

// head GEMM + softmax entropy -> ent[TT]
__global__ void __launch_bounds__(512)
gemm_ent_kernel(const bf16* __restrict__ A,
                const bf16* __restrict__ Bt,
                float* __restrict__ ent) {
    extern __shared__ __align__(16) char dsm[];
    bf16* sm = (bf16*)dsm;
    float acc[8][4];
    #pragma unroll
    for (int ni = 0; ni < 8; ni++)
        #pragma unroll
        for (int c = 0; c < 4; c++) acc[ni][c] = 0.f;

    const int rowBase = blockIdx.x * FBM;
    fused_mainloop(A, DM, Bt, DM, DM, rowBase, sm, acc);

    const int tid  = threadIdx.x;
    const int lane = tid & 31;
    const int g    = lane >> 2;
    const int tg   = lane & 3;
    const int warp = tid >> 5;
    const int wm   = warp & 3;
    const int wn   = warp >> 2;
    const int r0   = wm * 16 + g;
    const int r1   = r0 + 8;

    float mA = -1e30f, mB = -1e30f;
    #pragma unroll
    for (int ni = 0; ni < 8; ni++) {
        mA = fmaxf(mA, fmaxf(acc[ni][0], acc[ni][1]));
        mB = fmaxf(mB, fmaxf(acc[ni][2], acc[ni][3]));
    }
    mA = fmaxf(mA, __shfl_xor_sync(0xffffffffu, mA, 1));
    mA = fmaxf(mA, __shfl_xor_sync(0xffffffffu, mA, 2));
    mB = fmaxf(mB, __shfl_xor_sync(0xffffffffu, mB, 1));
    mB = fmaxf(mB, __shfl_xor_sync(0xffffffffu, mB, 2));

    float* sred = (float*)dsm;
    __syncthreads();
    if (tg == 0) { sred[r0 * 4 + wn] = mA; sred[r1 * 4 + wn] = mB; }
    __syncthreads();
    if (tid < 64)
        sred[256 + tid] = fmaxf(fmaxf(sred[tid*4], sred[tid*4+1]),
                                fmaxf(sred[tid*4+2], sred[tid*4+3]));
    __syncthreads();
    float rm0 = sred[256 + r0];
    float rm1 = sred[256 + r1];
    __syncthreads();

    float zA = 0.f, sAc = 0.f, zB = 0.f, sBc = 0.f;
    #pragma unroll
    for (int ni = 0; ni < 8; ni++) {
        float d0 = acc[ni][0] - rm0, d1 = acc[ni][1] - rm0;
        float d2 = acc[ni][2] - rm1, d3 = acc[ni][3] - rm1;
        float e0 = __expf(d0), e1 = __expf(d1), e2 = __expf(d2), e3 = __expf(d3);
        zA += e0 + e1;  sAc += e0 * d0 + e1 * d1;
        zB += e2 + e3;  sBc += e2 * d2 + e3 * d3;
    }
    zA  += __shfl_xor_sync(0xffffffffu, zA, 1);
    zA  += __shfl_xor_sync(0xffffffffu, zA, 2);
    sAc += __shfl_xor_sync(0xffffffffu, sAc, 1);
    sAc += __shfl_xor_sync(0xffffffffu, sAc, 2);
    zB  += __shfl_xor_sync(0xffffffffu, zB, 1);
    zB  += __shfl_xor_sync(0xffffffffu, zB, 2);
    sBc += __shfl_xor_sync(0xffffffffu, sBc, 1);
    sBc += __shfl_xor_sync(0xffffffffu, sBc, 2);

    if (tg == 0) {
        sred[r0 * 4 + wn] = zA;        sred[r1 * 4 + wn] = zB;
        sred[320 + r0 * 4 + wn] = sAc; sred[320 + r1 * 4 + wn] = sBc;
    }
    __syncthreads();
    if (tid < 64) {
        float Z = sred[tid*4] + sred[tid*4+1] + sred[tid*4+2] + sred[tid*4+3];
        float S = sred[320+tid*4] + sred[320+tid*4+1] + sred[320+tid*4+2] + sred[320+tid*4+3];
        ent[rowBase + tid] = (__logf(Z) - __fdividef(S, Z)) * (1.f / LOG_VOCAB_F);
    }
}

// ---------------------------------------------------------------------------
// Causal depthwise conv + bias + silu — register sliding window, 4 ch/thread
// ---------------------------------------------------------------------------
#define TCONV 16
__global__ void __launch_bounds__(256)
conv_silu_kernel(const bf16* __restrict__ xinzh,
                 const float* __restrict__ cw,
                 const float* __restrict__ cb,
                 bf16* __restrict__ xch) {
    const int tid = threadIdx.x;
    const int vec = tid & 127;
    const int tgrp = tid >> 7;
    const int dv = vec * 4;

    const int tokBlk = blockIdx.x;
    const int b = tokBlk / (SS / 32);
    const int sBase = (tokBlk % (SS / 32)) * 32 + tgrp * TCONV;

    float w[4][DCONV], bias[4];
    {
        float4 bv = *reinterpret_cast<const float4*>(&cb[dv]);
        bias[0] = bv.x; bias[1] = bv.y; bias[2] = bv.z; bias[3] = bv.w;
        #pragma unroll
        for (int j = 0; j < 4; j++) {
            float4 wv = *reinterpret_cast<const float4*>(&cw[(dv + j) * DCONV]);
            w[j][0] = wv.x; w[j][1] = wv.y; w[j][2] = wv.z; w[j][3] = wv.w;
        }
    }

    float p3[4], p2[4], p1[4];
    #pragma unroll
    for (int j = 0; j < 4; j++) { p3[j] = 0.f; p2[j] = 0.f; p1[j] = 0.f; }

    const bf16* rowBase = xinzh + (size_t)b * SS * (2 * DI) + dv;
    #define LOADROW(dst, s) { \
        uint2 raw = *reinterpret_cast<const uint2*>(rowBase + (size_t)(s) * (2 * DI)); \
        const __nv_bfloat162* h2 = reinterpret_cast<const __nv_bfloat162*>(&raw); \
        _Pragma("unroll") \
        for (int j = 0; j < 2; j++) { \
            float2 f = __bfloat1622float2(h2[j]); \
            dst[2*j] = f.x; dst[2*j+1] = f.y; } }

    if (sBase >= 3) { LOADROW(p3, sBase - 3); }
    if (sBase >= 2) { LOADROW(p2, sBase - 2); }
    if (sBase >= 1) { LOADROW(p1, sBase - 1); }

    bf16* outBase = xch + (size_t)b * SS * DI + dv;

    #pragma unroll
    for (int i = 0; i < TCONV; i++) {
        int s = sBase + i;
        float cur[4];
        LOADROW(cur, s);

        uint2 outv;
        uint32_t* o = reinterpret_cast<uint32_t*>(&outv);
        #pragma unroll
        for (int j = 0; j < 2; j++) {
            float a0 = bias[2*j], a1 = bias[2*j+1];
            a0 = fmaf(w[2*j][0],   p3[2*j],   a0);
            a1 = fmaf(w[2*j+1][0], p3[2*j+1], a1);
            a0 = fmaf(w[2*j][1],   p2[2*j],   a0);
            a1 = fmaf(w[2*j+1][1], p2[2*j+1], a1);
            a0 = fmaf(w[2*j][2],   p1[2*j],   a0);
            a1 = fmaf(w[2*j+1][2], p1[2*j+1], a1);
            a0 = fmaf(w[2*j][3],   cur[2*j],   a0);
            a1 = fmaf(w[2*j+1][3], cur[2*j+1], a1);
            float v0 = __fdividef(a0, 1.f + __expf(-a0));
            float v1 = __fdividef(a1, 1.f + __expf(-a1));
            o[j] = packbf(v0, v1);
        }
        *reinterpret_cast<uint2*>(outBase + (size_t)s * DI) = outv;

        #pragma unroll
        for (int j = 0; j < 4; j++) { p3[j] = p2[j]; p2[j] = p1[j]; p1[j] = cur[j]; }
    }
    #undef LOADROW
}

// ---------------------------------------------------------------------------
// Fused Mamba pointwise core (exp2-based MUFU path)
// ---------------------------------------------------------------------------
#define EW_TOKS 8
__global__ void mamba_ew_kernel(const bf16* __restrict__ dth,
                                const bf16* __restrict__ xch,
                                const bf16* __restrict__ xinzh,
                                const float* __restrict__ Bmat,
                                const float* __restrict__ Alog,
                                const float* __restrict__ dtb,
                                const float* __restrict__ Dp,
                                bf16* __restrict__ uh) {
    __shared__ float negAT[DSTATE][DI];   // pre-scaled by log2(e)
    __shared__ float sdtb[DI];
    __shared__ float sD[DI];
    __shared__ float sB[DSTATE];

    const int tid = threadIdx.x;
    for (int i = tid; i < DI * DSTATE; i += 256) {
        int d = i / DSTATE, n = i % DSTATE;
        negAT[n][d] = -__expf(Alog[i]) * LOG2E_F;
    }
    for (int i = tid; i < DI; i += 256) { sdtb[i] = dtb[i]; sD[i] = Dp[i]; }
    __syncthreads();

    for (int tok = 0; tok < EW_TOKS; tok++) {
        int t = blockIdx.x * EW_TOKS + tok;
        if (tid < DSTATE) sB[tid] = Bmat[t * DSTATE + tid];
        __syncthreads();

        #pragma unroll
        for (int rep = 0; rep < 2; rep++) {
            int d = tid + rep * 256;
            float v   = __bfloat162float(dth[(size_t)t * DI + d]) + sdtb[d];
            float dtv = fmaxf(v, 0.f) + __logf(1.f + __expf(-fabsf(v)));
            float xcv = __bfloat162float(xch[(size_t)t * DI + d]);
            float accn = 0.f;
            #pragma unroll
            for (int n = 0; n < DSTATE; n++)
                accn = fmaf(exp2f(negAT[n][d] * dtv), sB[n], accn);
            float yv = dtv * xcv * accn + sD[d] * xcv;
            float zv = __bfloat162float(xinzh[(size_t)t * (2 * DI) + DI + d]);
            uh[(size_t)t * DI + d] =
                __float2bfloat16_rn(yv * __fdividef(zv, 1.f + __expf(-zv)));
        }
        __syncthreads();
    }
}

// ---------------------------------------------------------------------------
// Parallel boundary computation (scan).
// ---------------------------------------------------------------------------
__global__ void boundary_kernel(const float* __restrict__ ent,
                                int* __restrict__ pstart,
                                int* __restrict__ np,
                                float* __restrict__ out_b2p) {
    __shared__ int sh[256];
    int b = blockIdx.x;
    int tid = threadIdx.x;
    int base = tid * 8;

    float e[8];
    #pragma unroll
    for (int i = 0; i < 8; i++) e[i] = ent[b * SS + base + i];

    int hard[8];
    int lasth = -1;
    #pragma unroll
    for (int i = 0; i < 8; i++) {
        hard[i] = (base + i == 0) || (e[i] > 0.5f);
        if (hard[i]) lasth = base + i;
    }

    sh[tid] = lasth;
    __syncthreads();
    for (int off = 1; off < 256; off <<= 1) {
        int u = sh[tid];
        int w = (tid >= off) ? sh[tid - off] : -1;
        __syncthreads();
        sh[tid] = max(u, w);
        __syncthreads();
    }
    int ph = (tid > 0) ? sh[tid - 1] : -1;

    int bnd[8];
    int cnt = 0;
    #pragma unroll
    for (int i = 0; i < 8; i++) {
        int s = base + i;
        if (hard[i]) ph = s;
        bnd[i] = hard[i] || (((s - ph) & 7) == 0);
        cnt += bnd[i];
    }

    __syncthreads();
    sh[tid] = cnt;
    __syncthreads();
    for (int off = 1; off < 256; off <<= 1) {
        int u = sh[tid];
        int w = (tid >= off) ? sh[tid - off] : 0;
        __syncthreads();
        sh[tid] = u + w;
        __syncthreads();
    }
    int pref = (tid > 0) ? sh[tid - 1] : 0;

    int c = 0;
    #pragma unroll
    for (int i = 0; i < 8; i++) {
        int s = base + i;
        c += bnd[i];
        int p = pref + c - 1;
        out_b2p[b * SS + s] = (float)p;
        if (bnd[i]) pstart[b * SS + p] = s;
    }
    if (tid == 255) np[b] = sh[255];
}

// ---------------------------------------------------------------------------
// Patch mean pooling
// ---------------------------------------------------------------------------
__global__ void pool_kernel(const float* __restrict__ be,
                            const int* __restrict__ pstart,
                            const int* __restrict__ np,
                            float* __restrict__ out_emb,
                            float* __restrict__ out_len) {
    int blk = blockIdx.x;
    int b = blk / SS;
    int p = blk - b * SS;
    int d = threadIdx.x;
    int npb = np[b];

    if (p < npb) {
        int s0 = pstart[b * SS + p];
        int s1 = (p + 1 < npb) ? pstart[b * SS + p + 1] : SS;
        float sum = 0.f;
        for (int s = s0; s < s1; s++)
            sum += be[(size_t)(b * SS + s) * DM + d];
        out_emb[(size_t)blk * DM + d] = sum / (float)(s1 - s0);
        if (d == 0) out_len[blk] = (float)(s1 - s0);
    } else {
        out_emb[(size_t)blk * DM + d] = 0.f;
        if (d == 0) out_len[blk] = 0.f;
    }
}

// ---------------------------------------------------------------------------
// Launch
// ---------------------------------------------------------------------------
#define FUSED_SMEM 51200

extern "C" void kernel_launch(void* const* d_in, const int* in_sizes, int n_in,
                              void* d_out, int out_size) {
    const int*   bytes = (const int*)  d_in[0];
    const float* be    = (const float*)d_in[1];
    const float* embW  = (const float*)d_in[2];
    const float* inW   = (const float*)d_in[3];
    const float* cw    = (const float*)d_in[4];
    const float* cb    = (const float*)d_in[5];
    const float* xpW   = (const float*)d_in[6];
    const float* dtW   = (const float*)d_in[7];
    const float* dtb   = (const float*)d_in[8];
    const float* Alog  = (const float*)d_in[9];
    const float* Dp    = (const float*)d_in[10];
    const float* outW  = (const float*)d_in[11];
    const float* nw    = (const float*)d_in[12];
    const float* headW = (const float*)d_in[13];
    float* out = (float*)d_out;

    static float *px=nullptr, *pB, *pent;
    static bf16 *pxh, *pxinzh, *pxch, *pdth, *puh, *pwbf, *pwdtm;
    static int *ppstart, *pnp;
    if (!px) {
        cudaGetSymbolAddress((void**)&px,     g_x);
        cudaGetSymbolAddress((void**)&pxh,    g_xh);
        cudaGetSymbolAddress((void**)&pxinzh, g_xinzh);
        cudaGetSymbolAddress((void**)&pxch,   g_xch);
        cudaGetSymbolAddress((void**)&pdth,   g_dth);
        cudaGetSymbolAddress((void**)&pB,     g_Bm);
        cudaGetSymbolAddress((void**)&puh,    g_uh);
        cudaGetSymbolAddress((void**)&pent,   g_ent);
        cudaGetSymbolAddress((void**)&pwbf,   g_wbf);
        cudaGetSymbolAddress((void**)&pwdtm,  g_wdtm);
        cudaGetSymbolAddress((void**)&ppstart,g_pstart);
        cudaGetSymbolAddress((void**)&pnp,    g_np);
        cudaFuncSetAttribute(gemm_rms_kernel,
            cudaFuncAttributeMaxDynamicSharedMemorySize, FUSED_SMEM);
        cudaFuncSetAttribute(gemm_ent_kernel,
            cudaFuncAttributeMaxDynamicSharedMemorySize, FUSED_SMEM);
        cudaFuncSetAttribute(mma_gemm128_kernel,
            cudaFuncAttributeMaxDynamicSharedMemorySize, G128_SMEM);
    }

    // 0) weight prep + embedding (single launch)
    prep_kernel<<<1384 + TT * DM / 1024, 256>>>(
        inW, dtW, outW, headW, xpW, bytes, embW, pwbf, pwdtm, px, pxh);

    // 1) two mamba blocks
    for (int l = 0; l < 2; l++) {
        // x @ in_proj -> xinz bf16  (N=1024, K=256)
        mma_gemm128_kernel<<<dim3(1024/GBN, TT/GBM), 256, G128_SMEM>>>(
            pxh, DM, pwbf + WOFF_IN(l), DM, pxinzh, 2 * DI, nullptr, 4096, DM);
        // depthwise conv + silu
        conv_silu_kernel<<<TT / 32, 256>>>(
            pxinzh, cw + (size_t)l * DI * DCONV, cb + (size_t)l * DI, pxch);
        // xc @ [dt_w | x_proj_B | pad] -> dt bf16 + Bm fp32  (N=576, K=512)
        mma_gemm128_kernel<<<dim3(NMERGE/GBN, TT/GBM), 256, G128_SMEM>>>(
            pxch, DI, pwdtm + (size_t)l * NMERGE * 512, DI,
            pdth, DI, pB, 512, DI);
        // fused pointwise core
        mamba_ew_kernel<<<TT / EW_TOKS, 256>>>(
            pdth, pxch, pxinzh, pB,
            Alog + (size_t)l * DI * DSTATE, dtb + (size_t)l * DI,
            Dp + (size_t)l * DI, puh);
        // u @ out_w + residual + rmsnorm (fused)
        gemm_rms_kernel<<<TT / FBM, 512, FUSED_SMEM>>>(
            puh, pwbf + WOFF_OUT(l), px, pxh, nw + (size_t)l * DM);
    }

    // 2) head + entropy (fused)
    gemm_ent_kernel<<<TT / FBM, 512, FUSED_SMEM>>>(pxh, pwbf + WOFF_HEAD, pent);

    // 3) boundaries (parallel scan)
    boundary_kernel<<<BB, 256>>>(pent, ppstart, pnp, out + (size_t)TT * DM + TT);

    // 4) patch pooling
    pool_kernel<<<BB * SS, 256>>>(be, ppstart, pnp, out, out + (size_t)TT * DM);
}